// round 9
// baseline (speedup 1.0000x reference)
#include <cuda_runtime.h>
#include <cuda_bf16.h>
#include <math.h>
#include <cstdint>

typedef unsigned int u32;

#define NN 50000
#define DF 128
#define HEADS 4
#define MAXE 800000

// ---------------- scratch (device globals; no allocations) ----------------
__device__ float g_agg[NN * DF];            // SAGE mean; later reused as GAT node output
__device__ float g_h[NN * DF];              // SAGE output
__device__ float g_aggh[NN * HEADS * DF];   // GAT per-head aggregated h
__device__ float g_as[NN * HEADS];
__device__ float g_ad[NN * HEADS];
__device__ float g_vs[DF * HEADS];
__device__ float g_vd[DF * HEADS];
__device__ float g_bstack[HEADS * DF * DF]; // rearranged 0.25*W_src  [512,128]
__device__ int   g_deg[NN];
__device__ int   g_rowptr[NN + 1];
__device__ int   g_cursor[NN];
__device__ int   g_csrsrc[MAXE];

__device__ __forceinline__ float lrelu(float v) { return v > 0.f ? v : 0.2f * v; }

// ---------------- CSR build ----------------
__global__ void k_zero_int(int* p, int n) {
    int i = blockIdx.x * blockDim.x + threadIdx.x;
    if (i < n) p[i] = 0;
}
__global__ void k_count(const int* __restrict__ ei, int E) {
    int e = blockIdx.x * blockDim.x + threadIdx.x;
    if (e < E) atomicAdd(&g_deg[ei[E + e]], 1);
}
__global__ void k_scan(int N) {
    __shared__ int warpsums[32];
    int tid = threadIdx.x;
    int CH = (N + 1023) >> 10;
    int base = tid * CH;
    int s = 0;
    for (int i = 0; i < CH; i++) {
        int idx = base + i;
        if (idx < N) s += g_deg[idx];
    }
    int lane = tid & 31, wid = tid >> 5;
    int v = s;
    #pragma unroll
    for (int o = 1; o < 32; o <<= 1) {
        int t = __shfl_up_sync(0xffffffff, v, o);
        if (lane >= o) v += t;
    }
    if (lane == 31) warpsums[wid] = v;
    __syncthreads();
    if (wid == 0) {
        int w = warpsums[lane];
        #pragma unroll
        for (int o = 1; o < 32; o <<= 1) {
            int t = __shfl_up_sync(0xffffffff, w, o);
            if (lane >= o) w += t;
        }
        warpsums[lane] = w;
    }
    __syncthreads();
    int offset = v - s + (wid > 0 ? warpsums[wid - 1] : 0);
    for (int i = 0; i < CH; i++) {
        int idx = base + i;
        if (idx < N) {
            g_rowptr[idx] = offset;
            offset += g_deg[idx];
            g_cursor[idx] = 0;
        }
    }
    if (tid == 1023) g_rowptr[N] = offset;
}
__global__ void k_csr_scatter(const int* __restrict__ ei, int E) {
    int e = blockIdx.x * blockDim.x + threadIdx.x;
    if (e >= E) return;
    int s = ei[e], d = ei[E + e];
    int pos = atomicAdd(&g_cursor[d], 1);
    g_csrsrc[g_rowptr[d] + pos] = s;
}

// ---------------- SAGE mean gather: warp per node, chunked for MLP ----------------
__global__ void k_sage_gather(const float* __restrict__ x, int N) {
    int gt = blockIdx.x * blockDim.x + threadIdx.x;
    int n = gt >> 5, lane = gt & 31;
    if (n >= N) return;
    int beg = g_rowptr[n], end = g_rowptr[n + 1];
    float4 acc = make_float4(0.f, 0.f, 0.f, 0.f);
    for (int b0 = beg; b0 < end; b0 += 32) {
        int i = b0 + lane;
        int idx = (i < end) ? g_csrsrc[i] : 0;
        int cnt = end - b0;
        if (cnt > 32) cnt = 32;
        for (int j = 0; j < cnt; j++) {
            int s = __shfl_sync(0xffffffffu, idx, j);
            float4 v = ((const float4*)(x + (size_t)s * DF))[lane];
            acc.x += v.x; acc.y += v.y; acc.z += v.z; acc.w += v.w;
        }
    }
    float inv = 1.f / fmaxf((float)(end - beg), 1.f);
    acc.x *= inv; acc.y *= inv; acc.z *= inv; acc.w *= inv;
    ((float4*)(g_agg + (size_t)n * DF))[lane] = acc;
}

// ---------------- tensor-core GEMM (split-bf16, fp32-accurate, prefetched) ----------------
// C = A1@B1 (+A2@B2) (+bias) (relu).  v = hi + lo; product = hi*hi + hi*lo + lo*hi.
#define TBM 128
#define TBN 128
#define TBK 32

__device__ __forceinline__ u32 ld2bf(const __nv_bfloat16* p) {
    return *reinterpret_cast<const u32*>(p);
}

__device__ __forceinline__ void mma_bf16(float* d, const u32* a, u32 b0, u32 b1) {
    asm volatile(
        "mma.sync.aligned.m16n8k16.row.col.f32.bf16.bf16.f32 "
        "{%0,%1,%2,%3},{%4,%5,%6,%7},{%8,%9},{%0,%1,%2,%3};"
        : "+f"(d[0]), "+f"(d[1]), "+f"(d[2]), "+f"(d[3])
        : "r"(a[0]), "r"(a[1]), "r"(a[2]), "r"(a[3]), "r"(b0), "r"(b1));
}

__global__ __launch_bounds__(512) void k_gemm_tc(
    const float* __restrict__ A1, const float* __restrict__ B1,
    const float* __restrict__ A2, const float* __restrict__ B2,
    const float* __restrict__ bias, float* __restrict__ C,
    int M, int K, int Ncols, int do_relu) {
    __shared__ __nv_bfloat16 Ah[TBM][40];
    __shared__ __nv_bfloat16 Al[TBM][40];
    __shared__ __nv_bfloat16 Bh[TBN][40];   // transposed: [n][k]
    __shared__ __nv_bfloat16 Bl[TBN][40];
    int tid = threadIdx.x;
    int w = tid >> 5, lane = tid & 31;
    int wm = w & 3, wn = w >> 2;            // 4 x 4 warps; warp tile 32(m) x 32(n)
    int m0 = blockIdx.x * TBM, n0 = blockIdx.y * TBN;
    float acc[2][4][4] = {};
    int npairs = A2 ? 2 : 1;
    int ktiles = K >> 5;
    int total = npairs * ktiles;

    int a_row = tid >> 2;          // 0..127
    int a_c = (tid & 3) * 8;       // 0,8,16,24
    int b_kr = tid >> 4;           // 0..31
    int b_c = (tid & 15) * 8;      // 0..120

    float4 ra0, ra1, rb0, rb1;
    // prefetch tile 0
    {
        const float* A = A1;
        const float* B = B1;
        ra0 = make_float4(0.f, 0.f, 0.f, 0.f); ra1 = ra0; rb0 = ra0; rb1 = ra0;
        if (m0 + a_row < M) {
            const float* ap = A + (size_t)(m0 + a_row) * K + a_c;
            ra0 = *(const float4*)ap;
            ra1 = *(const float4*)(ap + 4);
        }
        int bc = n0 + b_c;
        const float* bp = B + (size_t)b_kr * Ncols + bc;
        if (bc < Ncols) rb0 = *(const float4*)bp;
        if (bc + 4 < Ncols) rb1 = *(const float4*)(bp + 4);
    }

    for (int t = 0; t < total; t++) {
        // store staged tile to smem as hi/lo bf16
        {
            float av[8] = {ra0.x, ra0.y, ra0.z, ra0.w, ra1.x, ra1.y, ra1.z, ra1.w};
            #pragma unroll
            for (int j = 0; j < 8; j++) {
                __nv_bfloat16 hi = __float2bfloat16(av[j]);
                float rem = av[j] - __bfloat162float(hi);
                Ah[a_row][a_c + j] = hi;
                Al[a_row][a_c + j] = __float2bfloat16(rem);
            }
            float bv[8] = {rb0.x, rb0.y, rb0.z, rb0.w, rb1.x, rb1.y, rb1.z, rb1.w};
            #pragma unroll
            for (int j = 0; j < 8; j++) {
                __nv_bfloat16 hi = __float2bfloat16(bv[j]);
                float rem = bv[j] - __bfloat162float(hi);
                Bh[b_c + j][b_kr] = hi;
                Bl[b_c + j][b_kr] = __float2bfloat16(rem);
            }
        }
        __syncthreads();
        // prefetch next tile (overlaps with MMA below)
        if (t + 1 < total) {
            int tn = t + 1;
            int p = tn / ktiles;
            int k0 = (tn - p * ktiles) * TBK;
            const float* A = p ? A2 : A1;
            const float* B = p ? B2 : B1;
            ra0 = make_float4(0.f, 0.f, 0.f, 0.f); ra1 = ra0; rb0 = ra0; rb1 = ra0;
            if (m0 + a_row < M) {
                const float* ap = A + (size_t)(m0 + a_row) * K + k0 + a_c;
                ra0 = *(const float4*)ap;
                ra1 = *(const float4*)(ap + 4);
            }
            int bc = n0 + b_c;
            const float* bp = B + (size_t)(k0 + b_kr) * Ncols + bc;
            if (bc < Ncols) rb0 = *(const float4*)bp;
            if (bc + 4 < Ncols) rb1 = *(const float4*)(bp + 4);
        }
        // compute
        #pragma unroll
        for (int kk = 0; kk < TBK; kk += 16) {
            int kc = kk + (lane & 3) * 2;
            int kc8 = kc + 8;
            u32 bh[4][2];
            u32 bl[4][2];
            #pragma unroll
            for (int nt = 0; nt < 4; nt++) {
                int nc = wn * 32 + nt * 8 + (lane >> 2);
                bh[nt][0] = ld2bf(&Bh[nc][kc]);
                bh[nt][1] = ld2bf(&Bh[nc][kc8]);
                bl[nt][0] = ld2bf(&Bl[nc][kc]);
                bl[nt][1] = ld2bf(&Bl[nc][kc8]);
            }
            #pragma unroll
            for (int mt = 0; mt < 2; mt++) {
                int ar = wm * 32 + mt * 16 + (lane >> 2);
                int ar8 = ar + 8;
                u32 ah[4];
                u32 al[4];
                ah[0] = ld2bf(&Ah[ar][kc]);
                ah[1] = ld2bf(&Ah[ar8][kc]);
                ah[2] = ld2bf(&Ah[ar][kc8]);
                ah[3] = ld2bf(&Ah[ar8][kc8]);
                al[0] = ld2bf(&Al[ar][kc]);
                al[1] = ld2bf(&Al[ar8][kc]);
                al[2] = ld2bf(&Al[ar][kc8]);
                al[3] = ld2bf(&Al[ar8][kc8]);
                #pragma unroll
                for (int nt = 0; nt < 4; nt++) {
                    mma_bf16(acc[mt][nt], ah, bh[nt][0], bh[nt][1]);
                    mma_bf16(acc[mt][nt], ah, bl[nt][0], bl[nt][1]);
                    mma_bf16(acc[mt][nt], al, bh[nt][0], bh[nt][1]);
                }
            }
        }
        __syncthreads();
    }
    // epilogue
    #pragma unroll
    for (int mt = 0; mt < 2; mt++) {
        int r0 = m0 + wm * 32 + mt * 16 + (lane >> 2);
        #pragma unroll
        for (int nt = 0; nt < 4; nt++) {
            int c0 = n0 + wn * 32 + nt * 8 + (lane & 3) * 2;
            if (c0 >= Ncols) continue;
            float2 v0 = make_float2(acc[mt][nt][0], acc[mt][nt][1]);
            float2 v1 = make_float2(acc[mt][nt][2], acc[mt][nt][3]);
            if (bias) {
                float2 bb = *(const float2*)(bias + c0);
                v0.x += bb.x; v0.y += bb.y;
                v1.x += bb.x; v1.y += bb.y;
            }
            if (do_relu) {
                v0.x = fmaxf(v0.x, 0.f); v0.y = fmaxf(v0.y, 0.f);
                v1.x = fmaxf(v1.x, 0.f); v1.y = fmaxf(v1.y, 0.f);
            }
            if (r0 < M) *(float2*)(C + (size_t)r0 * Ncols + c0) = v0;
            if (r0 + 8 < M) *(float2*)(C + (size_t)(r0 + 8) * Ncols + c0) = v1;
        }
    }
}

// ---------------- attention-vector precompute ----------------
__global__ void k_att_vec(const float* __restrict__ Wsrc, const float* __restrict__ Wdst,
                          const float* __restrict__ atts, const float* __restrict__ attd) {
    int t = blockIdx.x * blockDim.x + threadIdx.x;
    if (t >= DF * HEADS) return;
    int k = t >> 2, h = t & 3;
    float s = 0.f, d = 0.f;
    for (int c = 0; c < DF; c++) {
        s = fmaf(Wsrc[(size_t)k * 512 + h * 128 + c], atts[h * 128 + c], s);
        d = fmaf(Wdst[(size_t)k * 512 + h * 128 + c], attd[h * 128 + c], d);
    }
    g_vs[k * 4 + h] = s;
    g_vd[k * 4 + h] = d;
}

// rearranged stacked GAT weight: Bstack[h*128+k][c] = 0.25 * W_src[k][h*128+c]
__global__ void k_bstack(const float* __restrict__ Wsrc) {
    int t = blockIdx.x * blockDim.x + threadIdx.x;
    if (t >= 512 * 128) return;
    int j = t >> 7, c = t & 127;
    int h = j >> 7, k = j & 127;
    g_bstack[t] = 0.25f * Wsrc[(size_t)k * 512 + h * 128 + c];
}

// ---------------- per-node a_s, a_d: warp per node ----------------
__global__ void k_asd(int N) {
    __shared__ float svs[DF * 4];
    __shared__ float svd[DF * 4];
    for (int i = threadIdx.x; i < DF * 4; i += blockDim.x) {
        svs[i] = g_vs[i];
        svd[i] = g_vd[i];
    }
    __syncthreads();
    int gt = blockIdx.x * blockDim.x + threadIdx.x;
    int n = gt >> 5, lane = gt & 31;
    if (n >= N) return;
    float as[4] = {}, ad[4] = {};
    #pragma unroll
    for (int kk = 0; kk < 4; kk++) {
        int k = lane + kk * 32;
        float hv = g_h[(size_t)n * DF + k];
        #pragma unroll
        for (int h = 0; h < 4; h++) {
            as[h] = fmaf(hv, svs[k * 4 + h], as[h]);
            ad[h] = fmaf(hv, svd[k * 4 + h], ad[h]);
        }
    }
    #pragma unroll
    for (int h = 0; h < 4; h++) {
        #pragma unroll
        for (int off = 16; off > 0; off >>= 1) {
            as[h] += __shfl_down_sync(0xffffffff, as[h], off);
            ad[h] += __shfl_down_sync(0xffffffff, ad[h], off);
        }
    }
    if (lane == 0) {
        #pragma unroll
        for (int h = 0; h < 4; h++) {
            g_as[n * 4 + h] = as[h];
            g_ad[n * 4 + h] = ad[h];
        }
    }
}

// ---------------- fused GAT softmax + aggregation: warp per node, chunked ----------------
__global__ void k_gat_gather(int N) {
    int gt = blockIdx.x * blockDim.x + threadIdx.x;
    int n = gt >> 5, lane = gt & 31;
    if (n >= N) return;
    int beg = g_rowptr[n], end = g_rowptr[n + 1];
    float4 ad = *(const float4*)(g_ad + (size_t)n * 4);

    // pass 1: segment max, lane-parallel
    float4 m = make_float4(-INFINITY, -INFINITY, -INFINITY, -INFINITY);
    for (int i = beg + lane; i < end; i += 32) {
        int s = g_csrsrc[i];
        float4 as = *(const float4*)(g_as + (size_t)s * 4);
        m.x = fmaxf(m.x, lrelu(as.x + ad.x));
        m.y = fmaxf(m.y, lrelu(as.y + ad.y));
        m.z = fmaxf(m.z, lrelu(as.z + ad.z));
        m.w = fmaxf(m.w, lrelu(as.w + ad.w));
    }
    #pragma unroll
    for (int o = 16; o > 0; o >>= 1) {
        m.x = fmaxf(m.x, __shfl_xor_sync(0xffffffff, m.x, o));
        m.y = fmaxf(m.y, __shfl_xor_sync(0xffffffff, m.y, o));
        m.z = fmaxf(m.z, __shfl_xor_sync(0xffffffff, m.z, o));
        m.w = fmaxf(m.w, __shfl_xor_sync(0xffffffff, m.w, o));
    }

    // pass 2: lane-parallel exp + den, shuffled weighted accumulate
    float4 denl = make_float4(0.f, 0.f, 0.f, 0.f);
    float4 a0 = make_float4(0.f, 0.f, 0.f, 0.f);
    float4 a1 = a0, a2 = a0, a3 = a0;
    for (int b0 = beg; b0 < end; b0 += 32) {
        int i = b0 + lane;
        int idx = 0;
        float4 wv = make_float4(0.f, 0.f, 0.f, 0.f);
        if (i < end) {
            idx = g_csrsrc[i];
            float4 as = *(const float4*)(g_as + (size_t)idx * 4);
            wv.x = __expf(lrelu(as.x + ad.x) - m.x);
            wv.y = __expf(lrelu(as.y + ad.y) - m.y);
            wv.z = __expf(lrelu(as.z + ad.z) - m.z);
            wv.w = __expf(lrelu(as.w + ad.w) - m.w);
            denl.x += wv.x; denl.y += wv.y; denl.z += wv.z; denl.w += wv.w;
        }
        int cnt = end - b0;
        if (cnt > 32) cnt = 32;
        for (int j = 0; j < cnt; j++) {
            int s = __shfl_sync(0xffffffffu, idx, j);
            float wx = __shfl_sync(0xffffffffu, wv.x, j);
            float wy = __shfl_sync(0xffffffffu, wv.y, j);
            float wz = __shfl_sync(0xffffffffu, wv.z, j);
            float ww = __shfl_sync(0xffffffffu, wv.w, j);
            float4 hv = ((const float4*)(g_h + (size_t)s * DF))[lane];
            a0.x = fmaf(hv.x, wx, a0.x); a0.y = fmaf(hv.y, wx, a0.y);
            a0.z = fmaf(hv.z, wx, a0.z); a0.w = fmaf(hv.w, wx, a0.w);
            a1.x = fmaf(hv.x, wy, a1.x); a1.y = fmaf(hv.y, wy, a1.y);
            a1.z = fmaf(hv.z, wy, a1.z); a1.w = fmaf(hv.w, wy, a1.w);
            a2.x = fmaf(hv.x, wz, a2.x); a2.y = fmaf(hv.y, wz, a2.y);
            a2.z = fmaf(hv.z, wz, a2.z); a2.w = fmaf(hv.w, wz, a2.w);
            a3.x = fmaf(hv.x, ww, a3.x); a3.y = fmaf(hv.y, ww, a3.y);
            a3.z = fmaf(hv.z, ww, a3.z); a3.w = fmaf(hv.w, ww, a3.w);
        }
    }
    #pragma unroll
    for (int o = 16; o > 0; o >>= 1) {
        denl.x += __shfl_xor_sync(0xffffffff, denl.x, o);
        denl.y += __shfl_xor_sync(0xffffffff, denl.y, o);
        denl.z += __shfl_xor_sync(0xffffffff, denl.z, o);
        denl.w += __shfl_xor_sync(0xffffffff, denl.w, o);
    }
    float i0 = denl.x > 0.f ? 1.f / denl.x : 0.f;
    float i1 = denl.y > 0.f ? 1.f / denl.y : 0.f;
    float i2 = denl.z > 0.f ? 1.f / denl.z : 0.f;
    float i3 = denl.w > 0.f ? 1.f / denl.w : 0.f;
    float4* outp = (float4*)(g_aggh + (size_t)n * 512);
    a0.x *= i0; a0.y *= i0; a0.z *= i0; a0.w *= i0;
    a1.x *= i1; a1.y *= i1; a1.z *= i1; a1.w *= i1;
    a2.x *= i2; a2.y *= i2; a2.z *= i2; a2.w *= i2;
    a3.x *= i3; a3.y *= i3; a3.z *= i3; a3.w *= i3;
    outp[0 * 32 + lane] = a0;
    outp[1 * 32 + lane] = a1;
    outp[2 * 32 + lane] = a2;
    outp[3 * 32 + lane] = a3;
}

// ---------------- launch ----------------
extern "C" void kernel_launch(void* const* d_in, const int* in_sizes, int n_in,
                              void* d_out, int out_size) {
    const float* x      = (const float*)d_in[0];
    const int*   ei     = (const int*)d_in[1];
    const float* W_l    = (const float*)d_in[2];
    const float* W_r    = (const float*)d_in[3];
    const float* b_sage = (const float*)d_in[4];
    const float* W_src  = (const float*)d_in[5];
    const float* W_dst  = (const float*)d_in[6];
    const float* att_s  = (const float*)d_in[7];
    const float* att_d  = (const float*)d_in[8];
    const float* b_gat  = (const float*)d_in[9];
    const float* W_lin  = (const float*)d_in[10];
    const float* b_lin  = (const float*)d_in[11];
    float* out = (float*)d_out;

    int N = in_sizes[0] / DF;
    int E = in_sizes[1] / 2;

    float *p_agg, *p_h, *p_aggh, *p_bstack;
    int* p_deg;
    cudaGetSymbolAddress((void**)&p_agg, g_agg);
    cudaGetSymbolAddress((void**)&p_h, g_h);
    cudaGetSymbolAddress((void**)&p_aggh, g_aggh);
    cudaGetSymbolAddress((void**)&p_bstack, g_bstack);
    cudaGetSymbolAddress((void**)&p_deg, g_deg);

    const int T = 256;
    int edgeBlocks = (E + T - 1) / T;
    int nodeWarpBlocks = (N * 32 + T - 1) / T;

    // ---- CSR build (launches 1-4) ----
    k_zero_int<<<(N + T - 1) / T, T>>>(p_deg, N);
    k_count<<<edgeBlocks, T>>>(ei, E);
    k_scan<<<1, 1024>>>(N);
    k_csr_scatter<<<edgeBlocks, T>>>(ei, E);

    // ---- SAGE (launches 5-6; gemm1 is launch #6 so ncu -s 5 profiles it) ----
    k_sage_gather<<<nodeWarpBlocks, T>>>(x, N);
    dim3 g1((N + TBM - 1) / TBM, (DF + TBN - 1) / TBN);
    k_gemm_tc<<<g1, 512>>>(p_agg, W_l, x, W_r, b_sage, p_h, N, 128, DF, 1);

    // ---- small precomputes ----
    k_att_vec<<<2, T>>>(W_src, W_dst, att_s, att_d);
    k_bstack<<<(512 * 128 + T - 1) / T, T>>>(W_src);

    // ---- GAT ----
    k_asd<<<nodeWarpBlocks, T>>>(N);
    k_gat_gather<<<nodeWarpBlocks, T>>>(N);
    k_gemm_tc<<<g1, 512>>>(p_aggh, p_bstack, nullptr, nullptr, b_gat, p_agg, N, 512, DF, 1);

    // ---- final linear ----
    dim3 g3((N + TBM - 1) / TBM, 1);
    k_gemm_tc<<<g3, 512>>>(p_agg, W_lin, nullptr, nullptr, b_lin, out, N, 128, 64, 0);
}

// round 11
// speedup vs baseline: 1.2135x; 1.2135x over previous
#include <cuda_runtime.h>
#include <cuda_bf16.h>
#include <math.h>
#include <cstdint>

typedef unsigned int u32;

#define NN 50000
#define DF 128
#define HEADS 4
#define MAXE 800000

// ---------------- scratch (device globals; no allocations) ----------------
__device__ float g_agg[NN * DF];            // SAGE mean; later reused as GAT node output
__device__ float g_h[NN * DF];              // SAGE output
__device__ float g_aggh[NN * HEADS * DF];   // GAT per-head aggregated h
__device__ float g_as[NN * HEADS];
__device__ float g_ad[NN * HEADS];
__device__ float g_vs[DF * HEADS];
__device__ float g_vd[DF * HEADS];
__device__ float g_bstack[HEADS * DF * DF]; // rearranged 0.25*W_src  [512,128]
__device__ int   g_deg[NN];
__device__ int   g_rowptr[NN + 1];
__device__ int   g_cursor[NN];
__device__ int   g_csrsrc[MAXE];

__device__ __forceinline__ float lrelu(float v) { return v > 0.f ? v : 0.2f * v; }

// ---------------- CSR build ----------------
__global__ void k_zero_int(int* p, int n) {
    int i = blockIdx.x * blockDim.x + threadIdx.x;
    if (i < n) p[i] = 0;
}
__global__ void k_count(const int* __restrict__ ei, int E) {
    int e = blockIdx.x * blockDim.x + threadIdx.x;
    if (e < E) atomicAdd(&g_deg[ei[E + e]], 1);
}
__global__ void k_scan(int N) {
    __shared__ int warpsums[32];
    int tid = threadIdx.x;
    int CH = (N + 1023) >> 10;
    int base = tid * CH;
    int s = 0;
    for (int i = 0; i < CH; i++) {
        int idx = base + i;
        if (idx < N) s += g_deg[idx];
    }
    int lane = tid & 31, wid = tid >> 5;
    int v = s;
    #pragma unroll
    for (int o = 1; o < 32; o <<= 1) {
        int t = __shfl_up_sync(0xffffffff, v, o);
        if (lane >= o) v += t;
    }
    if (lane == 31) warpsums[wid] = v;
    __syncthreads();
    if (wid == 0) {
        int w = warpsums[lane];
        #pragma unroll
        for (int o = 1; o < 32; o <<= 1) {
            int t = __shfl_up_sync(0xffffffff, w, o);
            if (lane >= o) w += t;
        }
        warpsums[lane] = w;
    }
    __syncthreads();
    int offset = v - s + (wid > 0 ? warpsums[wid - 1] : 0);
    for (int i = 0; i < CH; i++) {
        int idx = base + i;
        if (idx < N) {
            g_rowptr[idx] = offset;
            offset += g_deg[idx];
            g_cursor[idx] = 0;
        }
    }
    if (tid == 1023) g_rowptr[N] = offset;
}
__global__ void k_csr_scatter(const int* __restrict__ ei, int E) {
    int e = blockIdx.x * blockDim.x + threadIdx.x;
    if (e >= E) return;
    int s = ei[e], d = ei[E + e];
    int pos = atomicAdd(&g_cursor[d], 1);
    g_csrsrc[g_rowptr[d] + pos] = s;
}

// ---------------- SAGE mean gather: warp per node (R8 form) ----------------
__global__ void k_sage_gather(const float* __restrict__ x, int N) {
    int gt = blockIdx.x * blockDim.x + threadIdx.x;
    int n = gt >> 5, lane = gt & 31;
    if (n >= N) return;
    int beg = g_rowptr[n], end = g_rowptr[n + 1];
    float4 acc = make_float4(0.f, 0.f, 0.f, 0.f);
    for (int i = beg; i < end; i++) {
        int s = g_csrsrc[i];
        float4 v = ((const float4*)(x + (size_t)s * DF))[lane];
        acc.x += v.x; acc.y += v.y; acc.z += v.z; acc.w += v.w;
    }
    float inv = 1.f / fmaxf((float)(end - beg), 1.f);
    acc.x *= inv; acc.y *= inv; acc.z *= inv; acc.w *= inv;
    ((float4*)(g_agg + (size_t)n * DF))[lane] = acc;
}

// ---------------- tensor-core GEMM (split-bf16, double-buffered) ----------------
// C = A1@B1 (+A2@B2) (+bias) (relu).  v = hi + lo; product = hi*hi + hi*lo + lo*hi.
#define TBM 128
#define TBN 64
#define TBK 32
// dynamic smem layout (bf16 elements):
//   Ah: 2 stages x 128 x 40     Al: same
//   Bh: 2 stages x 64 x 40      Bl: same
#define A_ST (TBM * 40)
#define B_ST (TBN * 40)
#define OFF_AH 0
#define OFF_AL (2 * A_ST)
#define OFF_BH (4 * A_ST)
#define OFF_BL (4 * A_ST + 2 * B_ST)
#define SMEM_ELEMS (4 * A_ST + 4 * B_ST)
#define SMEM_BYTES (SMEM_ELEMS * 2)

__device__ __forceinline__ u32 ld2bf(const __nv_bfloat16* p) {
    return *reinterpret_cast<const u32*>(p);
}

__device__ __forceinline__ void mma_bf16(float* d, const u32* a, u32 b0, u32 b1) {
    asm volatile(
        "mma.sync.aligned.m16n8k16.row.col.f32.bf16.bf16.f32 "
        "{%0,%1,%2,%3},{%4,%5,%6,%7},{%8,%9},{%0,%1,%2,%3};"
        : "+f"(d[0]), "+f"(d[1]), "+f"(d[2]), "+f"(d[3])
        : "r"(a[0]), "r"(a[1]), "r"(a[2]), "r"(a[3]), "r"(b0), "r"(b1));
}

__global__ __launch_bounds__(256) void k_gemm_tc(
    const float* __restrict__ A1, const float* __restrict__ B1,
    const float* __restrict__ A2, const float* __restrict__ B2,
    const float* __restrict__ bias, float* __restrict__ C,
    int M, int K, int Ncols, int do_relu) {
    extern __shared__ __nv_bfloat16 sm[];
    __nv_bfloat16* Ah = sm + OFF_AH;
    __nv_bfloat16* Al = sm + OFF_AL;
    __nv_bfloat16* Bh = sm + OFF_BH;
    __nv_bfloat16* Bl = sm + OFF_BL;

    int tid = threadIdx.x;
    int w = tid >> 5, lane = tid & 31;
    int wm = w & 3, wn = w >> 2;       // 4 x 2 warp grid; warp tile 32x32
    int m0 = blockIdx.x * TBM, n0 = blockIdx.y * TBN;
    float acc[2][4][4] = {};
    int npairs = A2 ? 2 : 1;
    int ktiles = K >> 5;
    int total = npairs * ktiles;

    // staging indices (R8 pattern): A 4 float4/thread, B 2 float4/thread
    int a_row[4], a_c[4];
    #pragma unroll
    for (int i = 0; i < 4; i++) {
        int fid = tid * 4 + i;
        a_row[i] = fid >> 3;
        a_c[i] = (fid & 7) * 4;
    }
    int b_kr[2], b_c[2];
    #pragma unroll
    for (int i = 0; i < 2; i++) {
        int fid = tid * 2 + i;
        b_kr[i] = fid >> 4;
        b_c[i] = (fid & 15) * 4;
    }

    float4 ra[4], rb[2];
    // prefetch tile 0 into registers
    #pragma unroll
    for (int i = 0; i < 4; i++) {
        ra[i] = make_float4(0.f, 0.f, 0.f, 0.f);
        if (m0 + a_row[i] < M)
            ra[i] = *(const float4*)(A1 + (size_t)(m0 + a_row[i]) * K + a_c[i]);
    }
    #pragma unroll
    for (int i = 0; i < 2; i++)
        rb[i] = *(const float4*)(B1 + (size_t)b_kr[i] * Ncols + n0 + b_c[i]);

    // convert + store stage 0
    #pragma unroll
    for (int i = 0; i < 4; i++) {
        float vv[4] = {ra[i].x, ra[i].y, ra[i].z, ra[i].w};
        #pragma unroll
        for (int j = 0; j < 4; j++) {
            __nv_bfloat16 hi = __float2bfloat16(vv[j]);
            float rem = vv[j] - __bfloat162float(hi);
            Ah[a_row[i] * 40 + a_c[i] + j] = hi;
            Al[a_row[i] * 40 + a_c[i] + j] = __float2bfloat16(rem);
        }
    }
    #pragma unroll
    for (int i = 0; i < 2; i++) {
        float vv[4] = {rb[i].x, rb[i].y, rb[i].z, rb[i].w};
        #pragma unroll
        for (int j = 0; j < 4; j++) {
            __nv_bfloat16 hi = __float2bfloat16(vv[j]);
            float rem = vv[j] - __bfloat162float(hi);
            Bh[(b_c[i] + j) * 40 + b_kr[i]] = hi;
            Bl[(b_c[i] + j) * 40 + b_kr[i]] = __float2bfloat16(rem);
        }
    }
    __syncthreads();

    for (int t = 0; t < total; t++) {
        int cur = t & 1;
        int nxt = cur ^ 1;
        const __nv_bfloat16* cAh = Ah + cur * A_ST;
        const __nv_bfloat16* cAl = Al + cur * A_ST;
        const __nv_bfloat16* cBh = Bh + cur * B_ST;
        const __nv_bfloat16* cBl = Bl + cur * B_ST;

        // issue global loads for tile t+1 (hide behind MMA below)
        bool have_next = (t + 1 < total);
        if (have_next) {
            int tn = t + 1;
            int p = tn / ktiles;
            int k0 = (tn - p * ktiles) * TBK;
            const float* A = p ? A2 : A1;
            const float* B = p ? B2 : B1;
            #pragma unroll
            for (int i = 0; i < 4; i++) {
                ra[i] = make_float4(0.f, 0.f, 0.f, 0.f);
                if (m0 + a_row[i] < M)
                    ra[i] = *(const float4*)(A + (size_t)(m0 + a_row[i]) * K + k0 + a_c[i]);
            }
            #pragma unroll
            for (int i = 0; i < 2; i++)
                rb[i] = *(const float4*)(B + (size_t)(k0 + b_kr[i]) * Ncols + n0 + b_c[i]);
        }

        // compute from current stage
        #pragma unroll
        for (int kk = 0; kk < TBK; kk += 16) {
            int kc = kk + (lane & 3) * 2;
            int kc8 = kc + 8;
            u32 bhf[4][2];
            u32 blf[4][2];
            #pragma unroll
            for (int nt = 0; nt < 4; nt++) {
                int nc = wn * 32 + nt * 8 + (lane >> 2);
                bhf[nt][0] = ld2bf(&cBh[nc * 40 + kc]);
                bhf[nt][1] = ld2bf(&cBh[nc * 40 + kc8]);
                blf[nt][0] = ld2bf(&cBl[nc * 40 + kc]);
                blf[nt][1] = ld2bf(&cBl[nc * 40 + kc8]);
            }
            #pragma unroll
            for (int mt = 0; mt < 2; mt++) {
                int ar = wm * 32 + mt * 16 + (lane >> 2);
                int ar8 = ar + 8;
                u32 ah[4];
                u32 al[4];
                ah[0] = ld2bf(&cAh[ar * 40 + kc]);
                ah[1] = ld2bf(&cAh[ar8 * 40 + kc]);
                ah[2] = ld2bf(&cAh[ar * 40 + kc8]);
                ah[3] = ld2bf(&cAh[ar8 * 40 + kc8]);
                al[0] = ld2bf(&cAl[ar * 40 + kc]);
                al[1] = ld2bf(&cAl[ar8 * 40 + kc]);
                al[2] = ld2bf(&cAl[ar * 40 + kc8]);
                al[3] = ld2bf(&cAl[ar8 * 40 + kc8]);
                #pragma unroll
                for (int nt = 0; nt < 4; nt++) {
                    mma_bf16(acc[mt][nt], ah, bhf[nt][0], bhf[nt][1]);
                    mma_bf16(acc[mt][nt], ah, blf[nt][0], blf[nt][1]);
                    mma_bf16(acc[mt][nt], al, bhf[nt][0], bhf[nt][1]);
                }
            }
        }

        // convert + store tile t+1 into the other stage
        if (have_next) {
            __nv_bfloat16* nAh = Ah + nxt * A_ST;
            __nv_bfloat16* nAl = Al + nxt * A_ST;
            __nv_bfloat16* nBh = Bh + nxt * B_ST;
            __nv_bfloat16* nBl = Bl + nxt * B_ST;
            #pragma unroll
            for (int i = 0; i < 4; i++) {
                float vv[4] = {ra[i].x, ra[i].y, ra[i].z, ra[i].w};
                #pragma unroll
                for (int j = 0; j < 4; j++) {
                    __nv_bfloat16 hi = __float2bfloat16(vv[j]);
                    float rem = vv[j] - __bfloat162float(hi);
                    nAh[a_row[i] * 40 + a_c[i] + j] = hi;
                    nAl[a_row[i] * 40 + a_c[i] + j] = __float2bfloat16(rem);
                }
            }
            #pragma unroll
            for (int i = 0; i < 2; i++) {
                float vv[4] = {rb[i].x, rb[i].y, rb[i].z, rb[i].w};
                #pragma unroll
                for (int j = 0; j < 4; j++) {
                    __nv_bfloat16 hi = __float2bfloat16(vv[j]);
                    float rem = vv[j] - __bfloat162float(hi);
                    nBh[(b_c[i] + j) * 40 + b_kr[i]] = hi;
                    nBl[(b_c[i] + j) * 40 + b_kr[i]] = __float2bfloat16(rem);
                }
            }
        }
        __syncthreads();
    }
    // epilogue
    #pragma unroll
    for (int mt = 0; mt < 2; mt++) {
        int r0 = m0 + wm * 32 + mt * 16 + (lane >> 2);
        #pragma unroll
        for (int nt = 0; nt < 4; nt++) {
            int c0 = n0 + wn * 32 + nt * 8 + (lane & 3) * 2;
            float2 v0 = make_float2(acc[mt][nt][0], acc[mt][nt][1]);
            float2 v1 = make_float2(acc[mt][nt][2], acc[mt][nt][3]);
            if (bias) {
                float2 bb = *(const float2*)(bias + c0);
                v0.x += bb.x; v0.y += bb.y;
                v1.x += bb.x; v1.y += bb.y;
            }
            if (do_relu) {
                v0.x = fmaxf(v0.x, 0.f); v0.y = fmaxf(v0.y, 0.f);
                v1.x = fmaxf(v1.x, 0.f); v1.y = fmaxf(v1.y, 0.f);
            }
            if (r0 < M) *(float2*)(C + (size_t)r0 * Ncols + c0) = v0;
            if (r0 + 8 < M) *(float2*)(C + (size_t)(r0 + 8) * Ncols + c0) = v1;
        }
    }
}

// ---------------- attention-vector precompute ----------------
__global__ void k_att_vec(const float* __restrict__ Wsrc, const float* __restrict__ Wdst,
                          const float* __restrict__ atts, const float* __restrict__ attd) {
    int t = blockIdx.x * blockDim.x + threadIdx.x;
    if (t >= DF * HEADS) return;
    int k = t >> 2, h = t & 3;
    float s = 0.f, d = 0.f;
    for (int c = 0; c < DF; c++) {
        s = fmaf(Wsrc[(size_t)k * 512 + h * 128 + c], atts[h * 128 + c], s);
        d = fmaf(Wdst[(size_t)k * 512 + h * 128 + c], attd[h * 128 + c], d);
    }
    g_vs[k * 4 + h] = s;
    g_vd[k * 4 + h] = d;
}

// rearranged stacked GAT weight: Bstack[h*128+k][c] = 0.25 * W_src[k][h*128+c]
__global__ void k_bstack(const float* __restrict__ Wsrc) {
    int t = blockIdx.x * blockDim.x + threadIdx.x;
    if (t >= 512 * 128) return;
    int j = t >> 7, c = t & 127;
    int h = j >> 7, k = j & 127;
    g_bstack[t] = 0.25f * Wsrc[(size_t)k * 512 + h * 128 + c];
}

// ---------------- per-node a_s, a_d: warp per node ----------------
__global__ void k_asd(int N) {
    __shared__ float svs[DF * 4];
    __shared__ float svd[DF * 4];
    for (int i = threadIdx.x; i < DF * 4; i += blockDim.x) {
        svs[i] = g_vs[i];
        svd[i] = g_vd[i];
    }
    __syncthreads();
    int gt = blockIdx.x * blockDim.x + threadIdx.x;
    int n = gt >> 5, lane = gt & 31;
    if (n >= N) return;
    float as[4] = {}, ad[4] = {};
    #pragma unroll
    for (int kk = 0; kk < 4; kk++) {
        int k = lane + kk * 32;
        float hv = g_h[(size_t)n * DF + k];
        #pragma unroll
        for (int h = 0; h < 4; h++) {
            as[h] = fmaf(hv, svs[k * 4 + h], as[h]);
            ad[h] = fmaf(hv, svd[k * 4 + h], ad[h]);
        }
    }
    #pragma unroll
    for (int h = 0; h < 4; h++) {
        #pragma unroll
        for (int off = 16; off > 0; off >>= 1) {
            as[h] += __shfl_down_sync(0xffffffff, as[h], off);
            ad[h] += __shfl_down_sync(0xffffffff, ad[h], off);
        }
    }
    if (lane == 0) {
        #pragma unroll
        for (int h = 0; h < 4; h++) {
            g_as[n * 4 + h] = as[h];
            g_ad[n * 4 + h] = ad[h];
        }
    }
}

// ---------------- fused GAT softmax + aggregation: warp per node (R8 form) ----------------
__global__ void k_gat_gather(int N) {
    int gt = blockIdx.x * blockDim.x + threadIdx.x;
    int n = gt >> 5, lane = gt & 31;
    if (n >= N) return;
    int beg = g_rowptr[n], end = g_rowptr[n + 1];
    float4 ad = *(const float4*)(g_ad + (size_t)n * 4);

    float4 m = make_float4(-INFINITY, -INFINITY, -INFINITY, -INFINITY);
    for (int i = beg + lane; i < end; i += 32) {
        int s = g_csrsrc[i];
        float4 as = *(const float4*)(g_as + (size_t)s * 4);
        m.x = fmaxf(m.x, lrelu(as.x + ad.x));
        m.y = fmaxf(m.y, lrelu(as.y + ad.y));
        m.z = fmaxf(m.z, lrelu(as.z + ad.z));
        m.w = fmaxf(m.w, lrelu(as.w + ad.w));
    }
    #pragma unroll
    for (int o = 16; o > 0; o >>= 1) {
        m.x = fmaxf(m.x, __shfl_xor_sync(0xffffffff, m.x, o));
        m.y = fmaxf(m.y, __shfl_xor_sync(0xffffffff, m.y, o));
        m.z = fmaxf(m.z, __shfl_xor_sync(0xffffffff, m.z, o));
        m.w = fmaxf(m.w, __shfl_xor_sync(0xffffffff, m.w, o));
    }

    float4 den = make_float4(0.f, 0.f, 0.f, 0.f);
    float4 a0 = make_float4(0.f, 0.f, 0.f, 0.f);
    float4 a1 = a0, a2 = a0, a3 = a0;
    for (int i = beg; i < end; i++) {
        int s = g_csrsrc[i];
        float4 as = *(const float4*)(g_as + (size_t)s * 4);
        float4 w;
        w.x = __expf(lrelu(as.x + ad.x) - m.x);
        w.y = __expf(lrelu(as.y + ad.y) - m.y);
        w.z = __expf(lrelu(as.z + ad.z) - m.z);
        w.w = __expf(lrelu(as.w + ad.w) - m.w);
        den.x += w.x; den.y += w.y; den.z += w.z; den.w += w.w;
        float4 hv = ((const float4*)(g_h + (size_t)s * DF))[lane];
        a0.x = fmaf(hv.x, w.x, a0.x); a0.y = fmaf(hv.y, w.x, a0.y);
        a0.z = fmaf(hv.z, w.x, a0.z); a0.w = fmaf(hv.w, w.x, a0.w);
        a1.x = fmaf(hv.x, w.y, a1.x); a1.y = fmaf(hv.y, w.y, a1.y);
        a1.z = fmaf(hv.z, w.y, a1.z); a1.w = fmaf(hv.w, w.y, a1.w);
        a2.x = fmaf(hv.x, w.z, a2.x); a2.y = fmaf(hv.y, w.z, a2.y);
        a2.z = fmaf(hv.z, w.z, a2.z); a2.w = fmaf(hv.w, w.z, a2.w);
        a3.x = fmaf(hv.x, w.w, a3.x); a3.y = fmaf(hv.y, w.w, a3.y);
        a3.z = fmaf(hv.z, w.w, a3.z); a3.w = fmaf(hv.w, w.w, a3.w);
    }
    float i0 = den.x > 0.f ? 1.f / den.x : 0.f;
    float i1 = den.y > 0.f ? 1.f / den.y : 0.f;
    float i2 = den.z > 0.f ? 1.f / den.z : 0.f;
    float i3 = den.w > 0.f ? 1.f / den.w : 0.f;
    float4* outp = (float4*)(g_aggh + (size_t)n * 512);
    a0.x *= i0; a0.y *= i0; a0.z *= i0; a0.w *= i0;
    a1.x *= i1; a1.y *= i1; a1.z *= i1; a1.w *= i1;
    a2.x *= i2; a2.y *= i2; a2.z *= i2; a2.w *= i2;
    a3.x *= i3; a3.y *= i3; a3.z *= i3; a3.w *= i3;
    outp[0 * 32 + lane] = a0;
    outp[1 * 32 + lane] = a1;
    outp[2 * 32 + lane] = a2;
    outp[3 * 32 + lane] = a3;
}

// ---------------- launch ----------------
extern "C" void kernel_launch(void* const* d_in, const int* in_sizes, int n_in,
                              void* d_out, int out_size) {
    const float* x      = (const float*)d_in[0];
    const int*   ei     = (const int*)d_in[1];
    const float* W_l    = (const float*)d_in[2];
    const float* W_r    = (const float*)d_in[3];
    const float* b_sage = (const float*)d_in[4];
    const float* W_src  = (const float*)d_in[5];
    const float* W_dst  = (const float*)d_in[6];
    const float* att_s  = (const float*)d_in[7];
    const float* att_d  = (const float*)d_in[8];
    const float* b_gat  = (const float*)d_in[9];
    const float* W_lin  = (const float*)d_in[10];
    const float* b_lin  = (const float*)d_in[11];
    float* out = (float*)d_out;

    int N = in_sizes[0] / DF;
    int E = in_sizes[1] / 2;

    float *p_agg, *p_h, *p_aggh, *p_bstack;
    int* p_deg;
    cudaGetSymbolAddress((void**)&p_agg, g_agg);
    cudaGetSymbolAddress((void**)&p_h, g_h);
    cudaGetSymbolAddress((void**)&p_aggh, g_aggh);
    cudaGetSymbolAddress((void**)&p_bstack, g_bstack);
    cudaGetSymbolAddress((void**)&p_deg, g_deg);

    cudaFuncSetAttribute(k_gemm_tc, cudaFuncAttributeMaxDynamicSharedMemorySize, SMEM_BYTES);

    const int T = 256;
    int edgeBlocks = (E + T - 1) / T;
    int nodeWarpBlocks = (N * 32 + T - 1) / T;

    // ---- CSR build ----
    k_zero_int<<<(N + T - 1) / T, T>>>(p_deg, N);
    k_count<<<edgeBlocks, T>>>(ei, E);
    k_scan<<<1, 1024>>>(N);
    k_csr_scatter<<<edgeBlocks, T>>>(ei, E);

    // ---- small precomputes ----
    k_att_vec<<<2, T>>>(W_src, W_dst, att_s, att_d);
    k_bstack<<<(512 * 128 + T - 1) / T, T>>>(W_src);

    // ---- SAGE ----
    k_sage_gather<<<nodeWarpBlocks, T>>>(x, N);
    dim3 g1((N + TBM - 1) / TBM, DF / TBN);
    k_gemm_tc<<<g1, 256, SMEM_BYTES>>>(p_agg, W_l, x, W_r, b_sage, p_h, N, 128, DF, 1);

    // ---- GAT ----
    k_asd<<<nodeWarpBlocks, T>>>(N);
    k_gat_gather<<<nodeWarpBlocks, T>>>(N);
    k_gemm_tc<<<g1, 256, SMEM_BYTES>>>(p_aggh, p_bstack, nullptr, nullptr, b_gat, p_agg, N, 512, DF, 1);

    // ---- final linear ----
    dim3 g3((N + TBM - 1) / TBM, 1);
    k_gemm_tc<<<g3, 256, SMEM_BYTES>>>(p_agg, W_lin, nullptr, nullptr, b_lin, out, N, 128, 64, 0);
}

// round 12
// speedup vs baseline: 1.2383x; 1.0204x over previous
#include <cuda_runtime.h>
#include <cuda_bf16.h>
#include <math.h>
#include <cstdint>

typedef unsigned int u32;

#define NN 50000
#define DF 128
#define HEADS 4
#define MAXE 800000

// ---------------- scratch (device globals; no allocations) ----------------
__device__ float g_agg[NN * DF];            // SAGE mean; later reused as GAT node output
__device__ float g_h[NN * DF];              // SAGE output
__device__ float g_aggh[NN * HEADS * DF];   // GAT per-head aggregated h
__device__ float g_as[NN * HEADS];
__device__ float g_ad[NN * HEADS];
__device__ float g_vs[DF * HEADS];
__device__ float g_vd[DF * HEADS];
__device__ float g_bstack[HEADS * DF * DF]; // rearranged 0.25*W_src  [512,128]
__device__ int   g_deg[NN];
__device__ int   g_rowptr[NN + 1];
__device__ int   g_cursor[NN];
__device__ int   g_csrsrc[MAXE];

__device__ __forceinline__ float lrelu(float v) { return v > 0.f ? v : 0.2f * v; }

// ---------------- CSR build ----------------
__global__ void k_zero_int(int* p, int n) {
    int i = blockIdx.x * blockDim.x + threadIdx.x;
    if (i < n) p[i] = 0;
}
__global__ void k_count(const int* __restrict__ ei, int E) {
    int e = blockIdx.x * blockDim.x + threadIdx.x;
    if (e < E) atomicAdd(&g_deg[ei[E + e]], 1);
}
__global__ void k_scan(int N) {
    __shared__ int warpsums[32];
    int tid = threadIdx.x;
    int CH = (N + 1023) >> 10;
    int base = tid * CH;
    int s = 0;
    for (int i = 0; i < CH; i++) {
        int idx = base + i;
        if (idx < N) s += g_deg[idx];
    }
    int lane = tid & 31, wid = tid >> 5;
    int v = s;
    #pragma unroll
    for (int o = 1; o < 32; o <<= 1) {
        int t = __shfl_up_sync(0xffffffff, v, o);
        if (lane >= o) v += t;
    }
    if (lane == 31) warpsums[wid] = v;
    __syncthreads();
    if (wid == 0) {
        int w = warpsums[lane];
        #pragma unroll
        for (int o = 1; o < 32; o <<= 1) {
            int t = __shfl_up_sync(0xffffffff, w, o);
            if (lane >= o) w += t;
        }
        warpsums[lane] = w;
    }
    __syncthreads();
    int offset = v - s + (wid > 0 ? warpsums[wid - 1] : 0);
    for (int i = 0; i < CH; i++) {
        int idx = base + i;
        if (idx < N) {
            g_rowptr[idx] = offset;
            offset += g_deg[idx];
            g_cursor[idx] = 0;
        }
    }
    if (tid == 1023) g_rowptr[N] = offset;
}
__global__ void k_csr_scatter(const int* __restrict__ ei, int E) {
    int e = blockIdx.x * blockDim.x + threadIdx.x;
    if (e >= E) return;
    int s = ei[e], d = ei[E + e];
    int pos = atomicAdd(&g_cursor[d], 1);
    g_csrsrc[g_rowptr[d] + pos] = s;
}

// ---------------- SAGE mean gather: warp per node, chunked indices ----------------
__global__ void k_sage_gather(const float* __restrict__ x, int N) {
    int gt = blockIdx.x * blockDim.x + threadIdx.x;
    int n = gt >> 5, lane = gt & 31;
    if (n >= N) return;
    int beg = g_rowptr[n], end = g_rowptr[n + 1];
    float4 acc = make_float4(0.f, 0.f, 0.f, 0.f);
    for (int b0 = beg; b0 < end; b0 += 32) {
        int i = b0 + lane;
        int idx = (i < end) ? g_csrsrc[i] : 0;
        int cnt = end - b0;
        if (cnt > 32) cnt = 32;
        for (int j = 0; j < cnt; j++) {
            int s = __shfl_sync(0xffffffffu, idx, j);
            float4 v = ((const float4*)(x + (size_t)s * DF))[lane];
            acc.x += v.x; acc.y += v.y; acc.z += v.z; acc.w += v.w;
        }
    }
    float inv = 1.f / fmaxf((float)(end - beg), 1.f);
    acc.x *= inv; acc.y *= inv; acc.z *= inv; acc.w *= inv;
    ((float4*)(g_agg + (size_t)n * DF))[lane] = acc;
}

// ---------------- tensor-core GEMM (split-bf16, double-buffered) ----------------
// C = A1@B1 (+A2@B2) (+bias) (relu).  v = hi + lo; product = hi*hi + hi*lo + lo*hi.
#define TBM 128
#define TBN 64
#define TBK 32
#define A_ST (TBM * 40)
#define B_ST (TBN * 40)
#define OFF_AH 0
#define OFF_AL (2 * A_ST)
#define OFF_BH (4 * A_ST)
#define OFF_BL (4 * A_ST + 2 * B_ST)
#define SMEM_ELEMS (4 * A_ST + 4 * B_ST)
#define SMEM_BYTES (SMEM_ELEMS * 2)

__device__ __forceinline__ u32 ld2bf(const __nv_bfloat16* p) {
    return *reinterpret_cast<const u32*>(p);
}

__device__ __forceinline__ void mma_bf16(float* d, const u32* a, u32 b0, u32 b1) {
    asm volatile(
        "mma.sync.aligned.m16n8k16.row.col.f32.bf16.bf16.f32 "
        "{%0,%1,%2,%3},{%4,%5,%6,%7},{%8,%9},{%0,%1,%2,%3};"
        : "+f"(d[0]), "+f"(d[1]), "+f"(d[2]), "+f"(d[3])
        : "r"(a[0]), "r"(a[1]), "r"(a[2]), "r"(a[3]), "r"(b0), "r"(b1));
}

__global__ __launch_bounds__(256) void k_gemm_tc(
    const float* __restrict__ A1, const float* __restrict__ B1,
    const float* __restrict__ A2, const float* __restrict__ B2,
    const float* __restrict__ bias, float* __restrict__ C,
    int M, int K, int Ncols, int do_relu) {
    extern __shared__ __nv_bfloat16 sm[];
    __nv_bfloat16* Ah = sm + OFF_AH;
    __nv_bfloat16* Al = sm + OFF_AL;
    __nv_bfloat16* Bh = sm + OFF_BH;
    __nv_bfloat16* Bl = sm + OFF_BL;

    int tid = threadIdx.x;
    int w = tid >> 5, lane = tid & 31;
    int wm = w & 3, wn = w >> 2;       // 4 x 2 warp grid; warp tile 32x32
    int m0 = blockIdx.x * TBM, n0 = blockIdx.y * TBN;
    float acc[2][4][4] = {};
    int npairs = A2 ? 2 : 1;
    int ktiles = K >> 5;
    int total = npairs * ktiles;

    int a_row[4], a_c[4];
    #pragma unroll
    for (int i = 0; i < 4; i++) {
        int fid = tid * 4 + i;
        a_row[i] = fid >> 3;
        a_c[i] = (fid & 7) * 4;
    }
    int b_kr[2], b_c[2];
    #pragma unroll
    for (int i = 0; i < 2; i++) {
        int fid = tid * 2 + i;
        b_kr[i] = fid >> 4;
        b_c[i] = (fid & 15) * 4;
    }

    float4 ra[4], rb[2];
    #pragma unroll
    for (int i = 0; i < 4; i++) {
        ra[i] = make_float4(0.f, 0.f, 0.f, 0.f);
        if (m0 + a_row[i] < M)
            ra[i] = *(const float4*)(A1 + (size_t)(m0 + a_row[i]) * K + a_c[i]);
    }
    #pragma unroll
    for (int i = 0; i < 2; i++)
        rb[i] = *(const float4*)(B1 + (size_t)b_kr[i] * Ncols + n0 + b_c[i]);

    #pragma unroll
    for (int i = 0; i < 4; i++) {
        float vv[4] = {ra[i].x, ra[i].y, ra[i].z, ra[i].w};
        #pragma unroll
        for (int j = 0; j < 4; j++) {
            __nv_bfloat16 hi = __float2bfloat16(vv[j]);
            float rem = vv[j] - __bfloat162float(hi);
            Ah[a_row[i] * 40 + a_c[i] + j] = hi;
            Al[a_row[i] * 40 + a_c[i] + j] = __float2bfloat16(rem);
        }
    }
    #pragma unroll
    for (int i = 0; i < 2; i++) {
        float vv[4] = {rb[i].x, rb[i].y, rb[i].z, rb[i].w};
        #pragma unroll
        for (int j = 0; j < 4; j++) {
            __nv_bfloat16 hi = __float2bfloat16(vv[j]);
            float rem = vv[j] - __bfloat162float(hi);
            Bh[(b_c[i] + j) * 40 + b_kr[i]] = hi;
            Bl[(b_c[i] + j) * 40 + b_kr[i]] = __float2bfloat16(rem);
        }
    }
    __syncthreads();

    for (int t = 0; t < total; t++) {
        int cur = t & 1;
        int nxt = cur ^ 1;
        const __nv_bfloat16* cAh = Ah + cur * A_ST;
        const __nv_bfloat16* cAl = Al + cur * A_ST;
        const __nv_bfloat16* cBh = Bh + cur * B_ST;
        const __nv_bfloat16* cBl = Bl + cur * B_ST;

        bool have_next = (t + 1 < total);
        if (have_next) {
            int tn = t + 1;
            int p = tn / ktiles;
            int k0 = (tn - p * ktiles) * TBK;
            const float* A = p ? A2 : A1;
            const float* B = p ? B2 : B1;
            #pragma unroll
            for (int i = 0; i < 4; i++) {
                ra[i] = make_float4(0.f, 0.f, 0.f, 0.f);
                if (m0 + a_row[i] < M)
                    ra[i] = *(const float4*)(A + (size_t)(m0 + a_row[i]) * K + k0 + a_c[i]);
            }
            #pragma unroll
            for (int i = 0; i < 2; i++)
                rb[i] = *(const float4*)(B + (size_t)(k0 + b_kr[i]) * Ncols + n0 + b_c[i]);
        }

        #pragma unroll
        for (int kk = 0; kk < TBK; kk += 16) {
            int kc = kk + (lane & 3) * 2;
            int kc8 = kc + 8;
            u32 bhf[4][2];
            u32 blf[4][2];
            #pragma unroll
            for (int nt = 0; nt < 4; nt++) {
                int nc = wn * 32 + nt * 8 + (lane >> 2);
                bhf[nt][0] = ld2bf(&cBh[nc * 40 + kc]);
                bhf[nt][1] = ld2bf(&cBh[nc * 40 + kc8]);
                blf[nt][0] = ld2bf(&cBl[nc * 40 + kc]);
                blf[nt][1] = ld2bf(&cBl[nc * 40 + kc8]);
            }
            #pragma unroll
            for (int mt = 0; mt < 2; mt++) {
                int ar = wm * 32 + mt * 16 + (lane >> 2);
                int ar8 = ar + 8;
                u32 ah[4];
                u32 al[4];
                ah[0] = ld2bf(&cAh[ar * 40 + kc]);
                ah[1] = ld2bf(&cAh[ar8 * 40 + kc]);
                ah[2] = ld2bf(&cAh[ar * 40 + kc8]);
                ah[3] = ld2bf(&cAh[ar8 * 40 + kc8]);
                al[0] = ld2bf(&cAl[ar * 40 + kc]);
                al[1] = ld2bf(&cAl[ar8 * 40 + kc]);
                al[2] = ld2bf(&cAl[ar * 40 + kc8]);
                al[3] = ld2bf(&cAl[ar8 * 40 + kc8]);
                #pragma unroll
                for (int nt = 0; nt < 4; nt++) {
                    mma_bf16(acc[mt][nt], ah, bhf[nt][0], bhf[nt][1]);
                    mma_bf16(acc[mt][nt], ah, blf[nt][0], blf[nt][1]);
                    mma_bf16(acc[mt][nt], al, bhf[nt][0], bhf[nt][1]);
                }
            }
        }

        if (have_next) {
            __nv_bfloat16* nAh = Ah + nxt * A_ST;
            __nv_bfloat16* nAl = Al + nxt * A_ST;
            __nv_bfloat16* nBh = Bh + nxt * B_ST;
            __nv_bfloat16* nBl = Bl + nxt * B_ST;
            #pragma unroll
            for (int i = 0; i < 4; i++) {
                float vv[4] = {ra[i].x, ra[i].y, ra[i].z, ra[i].w};
                #pragma unroll
                for (int j = 0; j < 4; j++) {
                    __nv_bfloat16 hi = __float2bfloat16(vv[j]);
                    float rem = vv[j] - __bfloat162float(hi);
                    nAh[a_row[i] * 40 + a_c[i] + j] = hi;
                    nAl[a_row[i] * 40 + a_c[i] + j] = __float2bfloat16(rem);
                }
            }
            #pragma unroll
            for (int i = 0; i < 2; i++) {
                float vv[4] = {rb[i].x, rb[i].y, rb[i].z, rb[i].w};
                #pragma unroll
                for (int j = 0; j < 4; j++) {
                    __nv_bfloat16 hi = __float2bfloat16(vv[j]);
                    float rem = vv[j] - __bfloat162float(hi);
                    nBh[(b_c[i] + j) * 40 + b_kr[i]] = hi;
                    nBl[(b_c[i] + j) * 40 + b_kr[i]] = __float2bfloat16(rem);
                }
            }
        }
        __syncthreads();
    }
    // epilogue
    #pragma unroll
    for (int mt = 0; mt < 2; mt++) {
        int r0 = m0 + wm * 32 + mt * 16 + (lane >> 2);
        #pragma unroll
        for (int nt = 0; nt < 4; nt++) {
            int c0 = n0 + wn * 32 + nt * 8 + (lane & 3) * 2;
            float2 v0 = make_float2(acc[mt][nt][0], acc[mt][nt][1]);
            float2 v1 = make_float2(acc[mt][nt][2], acc[mt][nt][3]);
            if (bias) {
                float2 bb = *(const float2*)(bias + c0);
                v0.x += bb.x; v0.y += bb.y;
                v1.x += bb.x; v1.y += bb.y;
            }
            if (do_relu) {
                v0.x = fmaxf(v0.x, 0.f); v0.y = fmaxf(v0.y, 0.f);
                v1.x = fmaxf(v1.x, 0.f); v1.y = fmaxf(v1.y, 0.f);
            }
            if (r0 < M) *(float2*)(C + (size_t)r0 * Ncols + c0) = v0;
            if (r0 + 8 < M) *(float2*)(C + (size_t)(r0 + 8) * Ncols + c0) = v1;
        }
    }
}

// ---------------- attention-vector precompute ----------------
__global__ void k_att_vec(const float* __restrict__ Wsrc, const float* __restrict__ Wdst,
                          const float* __restrict__ atts, const float* __restrict__ attd) {
    int t = blockIdx.x * blockDim.x + threadIdx.x;
    if (t >= DF * HEADS) return;
    int k = t >> 2, h = t & 3;
    float s = 0.f, d = 0.f;
    for (int c = 0; c < DF; c++) {
        s = fmaf(Wsrc[(size_t)k * 512 + h * 128 + c], atts[h * 128 + c], s);
        d = fmaf(Wdst[(size_t)k * 512 + h * 128 + c], attd[h * 128 + c], d);
    }
    g_vs[k * 4 + h] = s;
    g_vd[k * 4 + h] = d;
}

// rearranged stacked GAT weight: Bstack[h*128+k][c] = 0.25 * W_src[k][h*128+c]
__global__ void k_bstack(const float* __restrict__ Wsrc) {
    int t = blockIdx.x * blockDim.x + threadIdx.x;
    if (t >= 512 * 128) return;
    int j = t >> 7, c = t & 127;
    int h = j >> 7, k = j & 127;
    g_bstack[t] = 0.25f * Wsrc[(size_t)k * 512 + h * 128 + c];
}

// ---------------- per-node a_s, a_d: warp per node ----------------
__global__ void k_asd(int N) {
    __shared__ float svs[DF * 4];
    __shared__ float svd[DF * 4];
    for (int i = threadIdx.x; i < DF * 4; i += blockDim.x) {
        svs[i] = g_vs[i];
        svd[i] = g_vd[i];
    }
    __syncthreads();
    int gt = blockIdx.x * blockDim.x + threadIdx.x;
    int n = gt >> 5, lane = gt & 31;
    if (n >= N) return;
    float as[4] = {}, ad[4] = {};
    #pragma unroll
    for (int kk = 0; kk < 4; kk++) {
        int k = lane + kk * 32;
        float hv = g_h[(size_t)n * DF + k];
        #pragma unroll
        for (int h = 0; h < 4; h++) {
            as[h] = fmaf(hv, svs[k * 4 + h], as[h]);
            ad[h] = fmaf(hv, svd[k * 4 + h], ad[h]);
        }
    }
    #pragma unroll
    for (int h = 0; h < 4; h++) {
        #pragma unroll
        for (int off = 16; off > 0; off >>= 1) {
            as[h] += __shfl_down_sync(0xffffffff, as[h], off);
            ad[h] += __shfl_down_sync(0xffffffff, ad[h], off);
        }
    }
    if (lane == 0) {
        #pragma unroll
        for (int h = 0; h < 4; h++) {
            g_as[n * 4 + h] = as[h];
            g_ad[n * 4 + h] = ad[h];
        }
    }
}

// ---------------- fused GAT softmax + aggregation: warp per node, chunked ----------------
__global__ void k_gat_gather(int N) {
    int gt = blockIdx.x * blockDim.x + threadIdx.x;
    int n = gt >> 5, lane = gt & 31;
    if (n >= N) return;
    int beg = g_rowptr[n], end = g_rowptr[n + 1];
    float4 ad = *(const float4*)(g_ad + (size_t)n * 4);

    // pass 1: segment max, lane-parallel
    float4 m = make_float4(-INFINITY, -INFINITY, -INFINITY, -INFINITY);
    for (int i = beg + lane; i < end; i += 32) {
        int s = g_csrsrc[i];
        float4 as = *(const float4*)(g_as + (size_t)s * 4);
        m.x = fmaxf(m.x, lrelu(as.x + ad.x));
        m.y = fmaxf(m.y, lrelu(as.y + ad.y));
        m.z = fmaxf(m.z, lrelu(as.z + ad.z));
        m.w = fmaxf(m.w, lrelu(as.w + ad.w));
    }
    #pragma unroll
    for (int o = 16; o > 0; o >>= 1) {
        m.x = fmaxf(m.x, __shfl_xor_sync(0xffffffff, m.x, o));
        m.y = fmaxf(m.y, __shfl_xor_sync(0xffffffff, m.y, o));
        m.z = fmaxf(m.z, __shfl_xor_sync(0xffffffff, m.z, o));
        m.w = fmaxf(m.w, __shfl_xor_sync(0xffffffff, m.w, o));
    }

    // pass 2: lane-parallel exp + den, shuffled weighted accumulate
    float4 denl = make_float4(0.f, 0.f, 0.f, 0.f);
    float4 a0 = make_float4(0.f, 0.f, 0.f, 0.f);
    float4 a1 = a0, a2 = a0, a3 = a0;
    for (int b0 = beg; b0 < end; b0 += 32) {
        int i = b0 + lane;
        int idx = 0;
        float4 wv = make_float4(0.f, 0.f, 0.f, 0.f);
        if (i < end) {
            idx = g_csrsrc[i];
            float4 as = *(const float4*)(g_as + (size_t)idx * 4);
            wv.x = __expf(lrelu(as.x + ad.x) - m.x);
            wv.y = __expf(lrelu(as.y + ad.y) - m.y);
            wv.z = __expf(lrelu(as.z + ad.z) - m.z);
            wv.w = __expf(lrelu(as.w + ad.w) - m.w);
            denl.x += wv.x; denl.y += wv.y; denl.z += wv.z; denl.w += wv.w;
        }
        int cnt = end - b0;
        if (cnt > 32) cnt = 32;
        for (int j = 0; j < cnt; j++) {
            int s = __shfl_sync(0xffffffffu, idx, j);
            float wx = __shfl_sync(0xffffffffu, wv.x, j);
            float wy = __shfl_sync(0xffffffffu, wv.y, j);
            float wz = __shfl_sync(0xffffffffu, wv.z, j);
            float ww = __shfl_sync(0xffffffffu, wv.w, j);
            float4 hv = ((const float4*)(g_h + (size_t)s * DF))[lane];
            a0.x = fmaf(hv.x, wx, a0.x); a0.y = fmaf(hv.y, wx, a0.y);
            a0.z = fmaf(hv.z, wx, a0.z); a0.w = fmaf(hv.w, wx, a0.w);
            a1.x = fmaf(hv.x, wy, a1.x); a1.y = fmaf(hv.y, wy, a1.y);
            a1.z = fmaf(hv.z, wy, a1.z); a1.w = fmaf(hv.w, wy, a1.w);
            a2.x = fmaf(hv.x, wz, a2.x); a2.y = fmaf(hv.y, wz, a2.y);
            a2.z = fmaf(hv.z, wz, a2.z); a2.w = fmaf(hv.w, wz, a2.w);
            a3.x = fmaf(hv.x, ww, a3.x); a3.y = fmaf(hv.y, ww, a3.y);
            a3.z = fmaf(hv.z, ww, a3.z); a3.w = fmaf(hv.w, ww, a3.w);
        }
    }
    #pragma unroll
    for (int o = 16; o > 0; o >>= 1) {
        denl.x += __shfl_xor_sync(0xffffffff, denl.x, o);
        denl.y += __shfl_xor_sync(0xffffffff, denl.y, o);
        denl.z += __shfl_xor_sync(0xffffffff, denl.z, o);
        denl.w += __shfl_xor_sync(0xffffffff, denl.w, o);
    }
    float i0 = denl.x > 0.f ? 1.f / denl.x : 0.f;
    float i1 = denl.y > 0.f ? 1.f / denl.y : 0.f;
    float i2 = denl.z > 0.f ? 1.f / denl.z : 0.f;
    float i3 = denl.w > 0.f ? 1.f / denl.w : 0.f;
    float4* outp = (float4*)(g_aggh + (size_t)n * 512);
    a0.x *= i0; a0.y *= i0; a0.z *= i0; a0.w *= i0;
    a1.x *= i1; a1.y *= i1; a1.z *= i1; a1.w *= i1;
    a2.x *= i2; a2.y *= i2; a2.z *= i2; a2.w *= i2;
    a3.x *= i3; a3.y *= i3; a3.z *= i3; a3.w *= i3;
    outp[0 * 32 + lane] = a0;
    outp[1 * 32 + lane] = a1;
    outp[2 * 32 + lane] = a2;
    outp[3 * 32 + lane] = a3;
}

// ---------------- launch ----------------
extern "C" void kernel_launch(void* const* d_in, const int* in_sizes, int n_in,
                              void* d_out, int out_size) {
    const float* x      = (const float*)d_in[0];
    const int*   ei     = (const int*)d_in[1];
    const float* W_l    = (const float*)d_in[2];
    const float* W_r    = (const float*)d_in[3];
    const float* b_sage = (const float*)d_in[4];
    const float* W_src  = (const float*)d_in[5];
    const float* W_dst  = (const float*)d_in[6];
    const float* att_s  = (const float*)d_in[7];
    const float* att_d  = (const float*)d_in[8];
    const float* b_gat  = (const float*)d_in[9];
    const float* W_lin  = (const float*)d_in[10];
    const float* b_lin  = (const float*)d_in[11];
    float* out = (float*)d_out;

    int N = in_sizes[0] / DF;
    int E = in_sizes[1] / 2;

    float *p_agg, *p_h, *p_aggh, *p_bstack;
    int* p_deg;
    cudaGetSymbolAddress((void**)&p_agg, g_agg);
    cudaGetSymbolAddress((void**)&p_h, g_h);
    cudaGetSymbolAddress((void**)&p_aggh, g_aggh);
    cudaGetSymbolAddress((void**)&p_bstack, g_bstack);
    cudaGetSymbolAddress((void**)&p_deg, g_deg);

    cudaFuncSetAttribute(k_gemm_tc, cudaFuncAttributeMaxDynamicSharedMemorySize, SMEM_BYTES);

    const int T = 256;
    int edgeBlocks = (E + T - 1) / T;
    int nodeWarpBlocks = (N * 32 + T - 1) / T;

    // ---- CSR build ----
    k_zero_int<<<(N + T - 1) / T, T>>>(p_deg, N);
    k_count<<<edgeBlocks, T>>>(ei, E);
    k_scan<<<1, 1024>>>(N);
    k_csr_scatter<<<edgeBlocks, T>>>(ei, E);

    // ---- small precomputes ----
    k_att_vec<<<2, T>>>(W_src, W_dst, att_s, att_d);
    k_bstack<<<(512 * 128 + T - 1) / T, T>>>(W_src);

    // ---- SAGE ----
    k_sage_gather<<<nodeWarpBlocks, T>>>(x, N);
    dim3 g1((N + TBM - 1) / TBM, DF / TBN);
    k_gemm_tc<<<g1, 256, SMEM_BYTES>>>(p_agg, W_l, x, W_r, b_sage, p_h, N, 128, DF, 1);

    // ---- GAT ----
    k_asd<<<nodeWarpBlocks, T>>>(N);
    k_gat_gather<<<nodeWarpBlocks, T>>>(N);
    k_gemm_tc<<<g1, 256, SMEM_BYTES>>>(p_aggh, p_bstack, nullptr, nullptr, b_gat, p_agg, N, 512, DF, 1);

    // ---- final linear ----
    dim3 g3((N + TBM - 1) / TBM, 1);
    k_gemm_tc<<<g3, 256, SMEM_BYTES>>>(p_agg, W_lin, nullptr, nullptr, b_lin, out, N, 128, 64, 0);
}

// round 15
// speedup vs baseline: 1.3657x; 1.1029x over previous
#include <cuda_runtime.h>
#include <cuda_bf16.h>
#include <math.h>
#include <cstdint>

typedef unsigned int u32;

#define NN 50000
#define DF 128
#define HEADS 4
#define MAXE 800000

// ---------------- scratch (device globals; no allocations) ----------------
__device__ float g_h[NN * DF];              // SAGE output (fp32, for asd/gat_gather)
__device__ float g_as[NN * HEADS];
__device__ float g_ad[NN * HEADS];
__device__ float g_vs[DF * HEADS];
__device__ float g_vd[DF * HEADS];
__device__ int   g_deg[NN];
__device__ int   g_rowptr[NN + 1];
__device__ int   g_cursor[NN];
__device__ int   g_csrsrc[MAXE];
// bf16 hi/lo pair arrays (GEMM operands, K-major)
__device__ __nv_bfloat16 g_xh[NN * DF],  g_xl[NN * DF];      // x pairs
__device__ __nv_bfloat16 g_sxh[NN * DF], g_sxl[NN * DF];     // SAGE mean pairs
__device__ __nv_bfloat16 g_ghh[NN * 512], g_ghl[NN * 512];   // GAT aggh pairs
__device__ __nv_bfloat16 g_goh[NN * DF], g_gol[NN * DF];     // GAT out pairs
__device__ __nv_bfloat16 g_wlh[128 * 128], g_wll[128 * 128]; // W_l^T pairs [n][k]
__device__ __nv_bfloat16 g_wrh[128 * 128], g_wrl[128 * 128];
__device__ __nv_bfloat16 g_bsh[128 * 512], g_bsl[128 * 512]; // 0.25*Wsrc stacked [n][kk]
__device__ __nv_bfloat16 g_wlinh[64 * 128], g_wlinl[64 * 128];

__device__ __forceinline__ float lrelu(float v) { return v > 0.f ? v : 0.2f * v; }

__device__ __forceinline__ u32 pack_bf(__nv_bfloat16 a, __nv_bfloat16 b) {
    return (u32)__bfloat16_as_ushort(a) | ((u32)__bfloat16_as_ushort(b) << 16);
}
__device__ __forceinline__ void store_pair4(__nv_bfloat16* dh, __nv_bfloat16* dl,
                                            size_t off, float4 v) {
    __nv_bfloat16 h0 = __float2bfloat16(v.x), h1 = __float2bfloat16(v.y);
    __nv_bfloat16 h2 = __float2bfloat16(v.z), h3 = __float2bfloat16(v.w);
    uint2 uh;
    uh.x = pack_bf(h0, h1);
    uh.y = pack_bf(h2, h3);
    __nv_bfloat16 l0 = __float2bfloat16(v.x - __bfloat162float(h0));
    __nv_bfloat16 l1 = __float2bfloat16(v.y - __bfloat162float(h1));
    __nv_bfloat16 l2 = __float2bfloat16(v.z - __bfloat162float(h2));
    __nv_bfloat16 l3 = __float2bfloat16(v.w - __bfloat162float(h3));
    uint2 ul;
    ul.x = pack_bf(l0, l1);
    ul.y = pack_bf(l2, l3);
    *(uint2*)(dh + off) = uh;
    *(uint2*)(dl + off) = ul;
}

// ---------------- CSR build ----------------
__global__ void k_zero_int(int* p, int n) {
    int i = blockIdx.x * blockDim.x + threadIdx.x;
    if (i < n) p[i] = 0;
}
__global__ void k_count(const int* __restrict__ ei, int E) {
    int e = blockIdx.x * blockDim.x + threadIdx.x;
    if (e < E) atomicAdd(&g_deg[ei[E + e]], 1);
}
__global__ void k_scan(int N) {
    __shared__ int warpsums[32];
    int tid = threadIdx.x;
    int CH = (N + 1023) >> 10;
    int base = tid * CH;
    int s = 0;
    for (int i = 0; i < CH; i++) {
        int idx = base + i;
        if (idx < N) s += g_deg[idx];
    }
    int lane = tid & 31, wid = tid >> 5;
    int v = s;
    #pragma unroll
    for (int o = 1; o < 32; o <<= 1) {
        int t = __shfl_up_sync(0xffffffff, v, o);
        if (lane >= o) v += t;
    }
    if (lane == 31) warpsums[wid] = v;
    __syncthreads();
    if (wid == 0) {
        int w = warpsums[lane];
        #pragma unroll
        for (int o = 1; o < 32; o <<= 1) {
            int t = __shfl_up_sync(0xffffffff, w, o);
            if (lane >= o) w += t;
        }
        warpsums[lane] = w;
    }
    __syncthreads();
    int offset = v - s + (wid > 0 ? warpsums[wid - 1] : 0);
    for (int i = 0; i < CH; i++) {
        int idx = base + i;
        if (idx < N) {
            g_rowptr[idx] = offset;
            offset += g_deg[idx];
            g_cursor[idx] = 0;
        }
    }
    if (tid == 1023) g_rowptr[N] = offset;
}
__global__ void k_csr_scatter(const int* __restrict__ ei, int E) {
    int e = blockIdx.x * blockDim.x + threadIdx.x;
    if (e >= E) return;
    int s = ei[e], d = ei[E + e];
    int pos = atomicAdd(&g_cursor[d], 1);
    g_csrsrc[g_rowptr[d] + pos] = s;
}

// ---------------- operand prep ----------------
__global__ void k_prep_x(const float* __restrict__ x, int n4) {
    int i = blockIdx.x * blockDim.x + threadIdx.x;
    if (i >= n4) return;
    float4 v = ((const float4*)x)[i];
    store_pair4(g_xh, g_xl, (size_t)i * 4, v);
}
__global__ void k_prep_wT(const float* __restrict__ src, __nv_bfloat16* dh,
                          __nv_bfloat16* dl, int K, int N, float scale) {
    int idx = blockIdx.x * blockDim.x + threadIdx.x;
    if (idx >= N * K) return;
    int n = idx / K, k = idx - n * K;
    float v = src[(size_t)k * N + n] * scale;
    __nv_bfloat16 hi = __float2bfloat16(v);
    dh[idx] = hi;
    dl[idx] = __float2bfloat16(v - __bfloat162float(hi));
}
__global__ void k_prep_bstack(const float* __restrict__ Wsrc) {
    int idx = blockIdx.x * blockDim.x + threadIdx.x;
    if (idx >= 128 * 512) return;
    int n = idx >> 9, kk = idx & 511;
    int k = kk & 127, h = kk >> 7;
    float v = 0.25f * Wsrc[(size_t)k * 512 + h * 128 + n];
    __nv_bfloat16 hi = __float2bfloat16(v);
    g_bsh[idx] = hi;
    g_bsl[idx] = __float2bfloat16(v - __bfloat162float(hi));
}

// ---------------- SAGE mean gather: warp per node, chunked -> bf16 pairs ----------------
__global__ void k_sage_gather(const float* __restrict__ x, int N) {
    int gt = blockIdx.x * blockDim.x + threadIdx.x;
    int n = gt >> 5, lane = gt & 31;
    if (n >= N) return;
    int beg = g_rowptr[n], end = g_rowptr[n + 1];
    float4 acc = make_float4(0.f, 0.f, 0.f, 0.f);
    for (int b0 = beg; b0 < end; b0 += 32) {
        int i = b0 + lane;
        int idx = (i < end) ? g_csrsrc[i] : 0;
        int cnt = end - b0;
        if (cnt > 32) cnt = 32;
        for (int j = 0; j < cnt; j++) {
            int s = __shfl_sync(0xffffffffu, idx, j);
            float4 v = ((const float4*)(x + (size_t)s * DF))[lane];
            acc.x += v.x; acc.y += v.y; acc.z += v.z; acc.w += v.w;
        }
    }
    float inv = 1.f / fmaxf((float)(end - beg), 1.f);
    acc.x *= inv; acc.y *= inv; acc.z *= inv; acc.w *= inv;
    store_pair4(g_sxh, g_sxl, (size_t)n * DF + lane * 4, acc);
}

// ---------------- HMMA GEMM (pre-split bf16 pairs, double-buffered) ----------------
// C = A1@B1 (+A2@B2) (+bias) (relu).  A: [M][Kin] pairs; B: [Ncols][Kin] pairs (K-major).
// Passes: Ah*Bh + Ah*Bl + Al*Bh, fp32 accum.
#define TBM 128
#define TBN 64
#define TBK 32
// stage layout (bytes): Ah 128*40*2=10240 | Al 10240 | Bh 64*40*2=5120 | Bl 5120 = 30720
#define STG_BYTES 30720
#define OFF_AL2 10240
#define OFF_BH2 20480
#define OFF_BL2 25600
#define SMEM_BYTES2 (2 * STG_BYTES)

__device__ __forceinline__ u32 ld2bf(const __nv_bfloat16* p) {
    return *reinterpret_cast<const u32*>(p);
}

__device__ __forceinline__ void mma_bf16(float* d, const u32* a, u32 b0, u32 b1) {
    asm volatile(
        "mma.sync.aligned.m16n8k16.row.col.f32.bf16.bf16.f32 "
        "{%0,%1,%2,%3},{%4,%5,%6,%7},{%8,%9},{%0,%1,%2,%3};"
        : "+f"(d[0]), "+f"(d[1]), "+f"(d[2]), "+f"(d[3])
        : "r"(a[0]), "r"(a[1]), "r"(a[2]), "r"(a[3]), "r"(b0), "r"(b1));
}

__global__ __launch_bounds__(256) void k_gemm_tc2(
    const __nv_bfloat16* __restrict__ Ah1, const __nv_bfloat16* __restrict__ Al1,
    const __nv_bfloat16* __restrict__ Bh1, const __nv_bfloat16* __restrict__ Bl1,
    const __nv_bfloat16* __restrict__ Ah2, const __nv_bfloat16* __restrict__ Al2,
    const __nv_bfloat16* __restrict__ Bh2, const __nv_bfloat16* __restrict__ Bl2,
    const float* __restrict__ bias, float* __restrict__ Cf,
    __nv_bfloat16* __restrict__ Ch, __nv_bfloat16* __restrict__ Cl,
    int M, int Kin, int Ncols, int do_relu) {
    extern __shared__ char smc[];
    int tid = threadIdx.x;
    int w = tid >> 5, lane = tid & 31;
    int wm = w & 3, wn = w >> 2;       // 4 x 2 warp grid; warp tile 32x32
    int m0 = blockIdx.x * TBM, n0 = blockIdx.y * TBN;
    float acc[2][4][4] = {};
    int npairs = Ah2 ? 2 : 1;
    int ktiles = Kin >> 5;
    int total = npairs * ktiles;

    // staging: A chunks 512 (2/thread), B chunks 256 (1/thread); 16B each
    int ar0 = (tid * 2) >> 2, ac0 = ((tid * 2) & 3) * 8;
    int ar1 = (tid * 2 + 1) >> 2, ac1 = ((tid * 2 + 1) & 3) * 8;
    int br = tid >> 2, bc = (tid & 3) * 8;

    uint4 pah[2], pal[2], pbh, pbl;
    // prefetch tile 0
    {
        const __nv_bfloat16* Ah = Ah1;
        const __nv_bfloat16* Al = Al1;
        pah[0] = make_uint4(0, 0, 0, 0); pah[1] = pah[0];
        pal[0] = pah[0]; pal[1] = pah[0];
        if (m0 + ar0 < M) {
            pah[0] = *(const uint4*)(Ah + (size_t)(m0 + ar0) * Kin + ac0);
            pal[0] = *(const uint4*)(Al + (size_t)(m0 + ar0) * Kin + ac0);
        }
        if (m0 + ar1 < M) {
            pah[1] = *(const uint4*)(Ah + (size_t)(m0 + ar1) * Kin + ac1);
            pal[1] = *(const uint4*)(Al + (size_t)(m0 + ar1) * Kin + ac1);
        }
        pbh = *(const uint4*)(Bh1 + (size_t)(n0 + br) * Kin + bc);
        pbl = *(const uint4*)(Bl1 + (size_t)(n0 + br) * Kin + bc);
    }
    // store stage 0
    {
        char* st = smc;
        *(uint4*)(st + (ar0 * 40 + ac0) * 2) = pah[0];
        *(uint4*)(st + (ar1 * 40 + ac1) * 2) = pah[1];
        *(uint4*)(st + OFF_AL2 + (ar0 * 40 + ac0) * 2) = pal[0];
        *(uint4*)(st + OFF_AL2 + (ar1 * 40 + ac1) * 2) = pal[1];
        *(uint4*)(st + OFF_BH2 + (br * 40 + bc) * 2) = pbh;
        *(uint4*)(st + OFF_BL2 + (br * 40 + bc) * 2) = pbl;
    }
    __syncthreads();

    for (int t = 0; t < total; t++) {
        int cur = t & 1;
        char* cs = smc + cur * STG_BYTES;
        const __nv_bfloat16* cAh = (const __nv_bfloat16*)cs;
        const __nv_bfloat16* cAl = (const __nv_bfloat16*)(cs + OFF_AL2);
        const __nv_bfloat16* cBh = (const __nv_bfloat16*)(cs + OFF_BH2);
        const __nv_bfloat16* cBl = (const __nv_bfloat16*)(cs + OFF_BL2);

        bool have_next = (t + 1 < total);
        if (have_next) {
            int tn = t + 1;
            int p = tn / ktiles;
            int k0 = (tn - p * ktiles) * TBK;
            const __nv_bfloat16* Ah = p ? Ah2 : Ah1;
            const __nv_bfloat16* Al = p ? Al2 : Al1;
            const __nv_bfloat16* Bh = p ? Bh2 : Bh1;
            const __nv_bfloat16* Bl = p ? Bl2 : Bl1;
            pah[0] = make_uint4(0, 0, 0, 0); pah[1] = pah[0];
            pal[0] = pah[0]; pal[1] = pah[0];
            if (m0 + ar0 < M) {
                pah[0] = *(const uint4*)(Ah + (size_t)(m0 + ar0) * Kin + k0 + ac0);
                pal[0] = *(const uint4*)(Al + (size_t)(m0 + ar0) * Kin + k0 + ac0);
            }
            if (m0 + ar1 < M) {
                pah[1] = *(const uint4*)(Ah + (size_t)(m0 + ar1) * Kin + k0 + ac1);
                pal[1] = *(const uint4*)(Al + (size_t)(m0 + ar1) * Kin + k0 + ac1);
            }
            pbh = *(const uint4*)(Bh + (size_t)(n0 + br) * Kin + k0 + bc);
            pbl = *(const uint4*)(Bl + (size_t)(n0 + br) * Kin + k0 + bc);
        }

        // compute
        #pragma unroll
        for (int kk = 0; kk < TBK; kk += 16) {
            int kc = kk + (lane & 3) * 2;
            int kc8 = kc + 8;
            u32 bhf[4][2];
            u32 blf[4][2];
            #pragma unroll
            for (int nt = 0; nt < 4; nt++) {
                int nc = wn * 32 + nt * 8 + (lane >> 2);
                bhf[nt][0] = ld2bf(&cBh[nc * 40 + kc]);
                bhf[nt][1] = ld2bf(&cBh[nc * 40 + kc8]);
                blf[nt][0] = ld2bf(&cBl[nc * 40 + kc]);
                blf[nt][1] = ld2bf(&cBl[nc * 40 + kc8]);
            }
            #pragma unroll
            for (int mt = 0; mt < 2; mt++) {
                int ar = wm * 32 + mt * 16 + (lane >> 2);
                int ar8 = ar + 8;
                u32 ah[4];
                u32 al[4];
                ah[0] = ld2bf(&cAh[ar * 40 + kc]);
                ah[1] = ld2bf(&cAh[ar8 * 40 + kc]);
                ah[2] = ld2bf(&cAh[ar * 40 + kc8]);
                ah[3] = ld2bf(&cAh[ar8 * 40 + kc8]);
                al[0] = ld2bf(&cAl[ar * 40 + kc]);
                al[1] = ld2bf(&cAl[ar8 * 40 + kc]);
                al[2] = ld2bf(&cAl[ar * 40 + kc8]);
                al[3] = ld2bf(&cAl[ar8 * 40 + kc8]);
                #pragma unroll
                for (int nt = 0; nt < 4; nt++) {
                    mma_bf16(acc[mt][nt], ah, bhf[nt][0], bhf[nt][1]);
                    mma_bf16(acc[mt][nt], ah, blf[nt][0], blf[nt][1]);
                    mma_bf16(acc[mt][nt], al, bhf[nt][0], bhf[nt][1]);
                }
            }
        }

        if (have_next) {
            char* ns = smc + (cur ^ 1) * STG_BYTES;
            *(uint4*)(ns + (ar0 * 40 + ac0) * 2) = pah[0];
            *(uint4*)(ns + (ar1 * 40 + ac1) * 2) = pah[1];
            *(uint4*)(ns + OFF_AL2 + (ar0 * 40 + ac0) * 2) = pal[0];
            *(uint4*)(ns + OFF_AL2 + (ar1 * 40 + ac1) * 2) = pal[1];
            *(uint4*)(ns + OFF_BH2 + (br * 40 + bc) * 2) = pbh;
            *(uint4*)(ns + OFF_BL2 + (br * 40 + bc) * 2) = pbl;
        }
        __syncthreads();
    }
    // epilogue
    #pragma unroll
    for (int mt = 0; mt < 2; mt++) {
        int r0 = m0 + wm * 32 + mt * 16 + (lane >> 2);
        #pragma unroll
        for (int nt = 0; nt < 4; nt++) {
            int c0 = n0 + wn * 32 + nt * 8 + (lane & 3) * 2;
            float2 v0 = make_float2(acc[mt][nt][0], acc[mt][nt][1]);
            float2 v1 = make_float2(acc[mt][nt][2], acc[mt][nt][3]);
            if (bias) {
                float2 bb = *(const float2*)(bias + c0);
                v0.x += bb.x; v0.y += bb.y;
                v1.x += bb.x; v1.y += bb.y;
            }
            if (do_relu) {
                v0.x = fmaxf(v0.x, 0.f); v0.y = fmaxf(v0.y, 0.f);
                v1.x = fmaxf(v1.x, 0.f); v1.y = fmaxf(v1.y, 0.f);
            }
            if (Cf) {
                if (r0 < M) *(float2*)(Cf + (size_t)r0 * Ncols + c0) = v0;
                if (r0 + 8 < M) *(float2*)(Cf + (size_t)(r0 + 8) * Ncols + c0) = v1;
            } else {
                if (r0 < M) {
                    size_t oo = (size_t)r0 * Ncols + c0;
                    __nv_bfloat16 h0 = __float2bfloat16(v0.x);
                    __nv_bfloat16 h1 = __float2bfloat16(v0.y);
                    *(u32*)(Ch + oo) = pack_bf(h0, h1);
                    *(u32*)(Cl + oo) = pack_bf(
                        __float2bfloat16(v0.x - __bfloat162float(h0)),
                        __float2bfloat16(v0.y - __bfloat162float(h1)));
                }
                if (r0 + 8 < M) {
                    size_t oo = (size_t)(r0 + 8) * Ncols + c0;
                    __nv_bfloat16 h0 = __float2bfloat16(v1.x);
                    __nv_bfloat16 h1 = __float2bfloat16(v1.y);
                    *(u32*)(Ch + oo) = pack_bf(h0, h1);
                    *(u32*)(Cl + oo) = pack_bf(
                        __float2bfloat16(v1.x - __bfloat162float(h0)),
                        __float2bfloat16(v1.y - __bfloat162float(h1)));
                }
            }
        }
    }
}

// ---------------- attention-vector precompute ----------------
__global__ void k_att_vec(const float* __restrict__ Wsrc, const float* __restrict__ Wdst,
                          const float* __restrict__ atts, const float* __restrict__ attd) {
    int t = blockIdx.x * blockDim.x + threadIdx.x;
    if (t >= DF * HEADS) return;
    int k = t >> 2, h = t & 3;
    float s = 0.f, d = 0.f;
    for (int c = 0; c < DF; c++) {
        s = fmaf(Wsrc[(size_t)k * 512 + h * 128 + c], atts[h * 128 + c], s);
        d = fmaf(Wdst[(size_t)k * 512 + h * 128 + c], attd[h * 128 + c], d);
    }
    g_vs[k * 4 + h] = s;
    g_vd[k * 4 + h] = d;
}

// ---------------- per-node a_s, a_d: warp per node ----------------
__global__ void k_asd(int N) {
    __shared__ float svs[DF * 4];
    __shared__ float svd[DF * 4];
    for (int i = threadIdx.x; i < DF * 4; i += blockDim.x) {
        svs[i] = g_vs[i];
        svd[i] = g_vd[i];
    }
    __syncthreads();
    int gt = blockIdx.x * blockDim.x + threadIdx.x;
    int n = gt >> 5, lane = gt & 31;
    if (n >= N) return;
    float as[4] = {}, ad[4] = {};
    #pragma unroll
    for (int kk = 0; kk < 4; kk++) {
        int k = lane + kk * 32;
        float hv = g_h[(size_t)n * DF + k];
        #pragma unroll
        for (int h = 0; h < 4; h++) {
            as[h] = fmaf(hv, svs[k * 4 + h], as[h]);
            ad[h] = fmaf(hv, svd[k * 4 + h], ad[h]);
        }
    }
    #pragma unroll
    for (int h = 0; h < 4; h++) {
        #pragma unroll
        for (int off = 16; off > 0; off >>= 1) {
            as[h] += __shfl_down_sync(0xffffffff, as[h], off);
            ad[h] += __shfl_down_sync(0xffffffff, ad[h], off);
        }
    }
    if (lane == 0) {
        #pragma unroll
        for (int h = 0; h < 4; h++) {
            g_as[n * 4 + h] = as[h];
            g_ad[n * 4 + h] = ad[h];
        }
    }
}

// ---------------- fused GAT softmax + aggregation -> bf16 pairs ----------------
__global__ void k_gat_gather(int N) {
    int gt = blockIdx.x * blockDim.x + threadIdx.x;
    int n = gt >> 5, lane = gt & 31;
    if (n >= N) return;
    int beg = g_rowptr[n], end = g_rowptr[n + 1];
    float4 ad = *(const float4*)(g_ad + (size_t)n * 4);

    float4 m = make_float4(-INFINITY, -INFINITY, -INFINITY, -INFINITY);
    for (int i = beg + lane; i < end; i += 32) {
        int s = g_csrsrc[i];
        float4 as = *(const float4*)(g_as + (size_t)s * 4);
        m.x = fmaxf(m.x, lrelu(as.x + ad.x));
        m.y = fmaxf(m.y, lrelu(as.y + ad.y));
        m.z = fmaxf(m.z, lrelu(as.z + ad.z));
        m.w = fmaxf(m.w, lrelu(as.w + ad.w));
    }
    #pragma unroll
    for (int o = 16; o > 0; o >>= 1) {
        m.x = fmaxf(m.x, __shfl_xor_sync(0xffffffff, m.x, o));
        m.y = fmaxf(m.y, __shfl_xor_sync(0xffffffff, m.y, o));
        m.z = fmaxf(m.z, __shfl_xor_sync(0xffffffff, m.z, o));
        m.w = fmaxf(m.w, __shfl_xor_sync(0xffffffff, m.w, o));
    }

    float4 denl = make_float4(0.f, 0.f, 0.f, 0.f);
    float4 a0 = make_float4(0.f, 0.f, 0.f, 0.f);
    float4 a1 = a0, a2 = a0, a3 = a0;
    for (int b0 = beg; b0 < end; b0 += 32) {
        int i = b0 + lane;
        int idx = 0;
        float4 wv = make_float4(0.f, 0.f, 0.f, 0.f);
        if (i < end) {
            idx = g_csrsrc[i];
            float4 as = *(const float4*)(g_as + (size_t)idx * 4);
            wv.x = __expf(lrelu(as.x + ad.x) - m.x);
            wv.y = __expf(lrelu(as.y + ad.y) - m.y);
            wv.z = __expf(lrelu(as.z + ad.z) - m.z);
            wv.w = __expf(lrelu(as.w + ad.w) - m.w);
            denl.x += wv.x; denl.y += wv.y; denl.z += wv.z; denl.w += wv.w;
        }
        int cnt = end - b0;
        if (cnt > 32) cnt = 32;
        for (int j = 0; j < cnt; j++) {
            int s = __shfl_sync(0xffffffffu, idx, j);
            float wx = __shfl_sync(0xffffffffu, wv.x, j);
            float wy = __shfl_sync(0xffffffffu, wv.y, j);
            float wz = __shfl_sync(0xffffffffu, wv.z, j);
            float ww = __shfl_sync(0xffffffffu, wv.w, j);
            float4 hv = ((const float4*)(g_h + (size_t)s * DF))[lane];
            a0.x = fmaf(hv.x, wx, a0.x); a0.y = fmaf(hv.y, wx, a0.y);
            a0.z = fmaf(hv.z, wx, a0.z); a0.w = fmaf(hv.w, wx, a0.w);
            a1.x = fmaf(hv.x, wy, a1.x); a1.y = fmaf(hv.y, wy, a1.y);
            a1.z = fmaf(hv.z, wy, a1.z); a1.w = fmaf(hv.w, wy, a1.w);
            a2.x = fmaf(hv.x, wz, a2.x); a2.y = fmaf(hv.y, wz, a2.y);
            a2.z = fmaf(hv.z, wz, a2.z); a2.w = fmaf(hv.w, wz, a2.w);
            a3.x = fmaf(hv.x, ww, a3.x); a3.y = fmaf(hv.y, ww, a3.y);
            a3.z = fmaf(hv.z, ww, a3.z); a3.w = fmaf(hv.w, ww, a3.w);
        }
    }
    #pragma unroll
    for (int o = 16; o > 0; o >>= 1) {
        denl.x += __shfl_xor_sync(0xffffffff, denl.x, o);
        denl.y += __shfl_xor_sync(0xffffffff, denl.y, o);
        denl.z += __shfl_xor_sync(0xffffffff, denl.z, o);
        denl.w += __shfl_xor_sync(0xffffffff, denl.w, o);
    }
    float i0 = denl.x > 0.f ? 1.f / denl.x : 0.f;
    float i1 = denl.y > 0.f ? 1.f / denl.y : 0.f;
    float i2 = denl.z > 0.f ? 1.f / denl.z : 0.f;
    float i3 = denl.w > 0.f ? 1.f / denl.w : 0.f;
    a0.x *= i0; a0.y *= i0; a0.z *= i0; a0.w *= i0;
    a1.x *= i1; a1.y *= i1; a1.z *= i1; a1.w *= i1;
    a2.x *= i2; a2.y *= i2; a2.z *= i2; a2.w *= i2;
    a3.x *= i3; a3.y *= i3; a3.z *= i3; a3.w *= i3;
    size_t ob = (size_t)n * 512 + lane * 4;
    store_pair4(g_ghh, g_ghl, ob + 0 * 128, a0);
    store_pair4(g_ghh, g_ghl, ob + 1 * 128, a1);
    store_pair4(g_ghh, g_ghl, ob + 2 * 128, a2);
    store_pair4(g_ghh, g_ghl, ob + 3 * 128, a3);
}

// ---------------- launch ----------------
extern "C" void kernel_launch(void* const* d_in, const int* in_sizes, int n_in,
                              void* d_out, int out_size) {
    const float* x      = (const float*)d_in[0];
    const int*   ei     = (const int*)d_in[1];
    const float* W_l    = (const float*)d_in[2];
    const float* W_r    = (const float*)d_in[3];
    const float* b_sage = (const float*)d_in[4];
    const float* W_src  = (const float*)d_in[5];
    const float* W_dst  = (const float*)d_in[6];
    const float* att_s  = (const float*)d_in[7];
    const float* att_d  = (const float*)d_in[8];
    const float* b_gat  = (const float*)d_in[9];
    const float* W_lin  = (const float*)d_in[10];
    const float* b_lin  = (const float*)d_in[11];
    float* out = (float*)d_out;

    int N = in_sizes[0] / DF;
    int E = in_sizes[1] / 2;

    float* p_h;
    int* p_deg;
    __nv_bfloat16 *p_xh, *p_xl, *p_sxh, *p_sxl, *p_ghh, *p_ghl, *p_goh, *p_gol;
    __nv_bfloat16 *p_wlh, *p_wll, *p_wrh, *p_wrl, *p_bsh, *p_bsl, *p_wlinh, *p_wlinl;
    cudaGetSymbolAddress((void**)&p_h, g_h);
    cudaGetSymbolAddress((void**)&p_deg, g_deg);
    cudaGetSymbolAddress((void**)&p_xh, g_xh);
    cudaGetSymbolAddress((void**)&p_xl, g_xl);
    cudaGetSymbolAddress((void**)&p_sxh, g_sxh);
    cudaGetSymbolAddress((void**)&p_sxl, g_sxl);
    cudaGetSymbolAddress((void**)&p_ghh, g_ghh);
    cudaGetSymbolAddress((void**)&p_ghl, g_ghl);
    cudaGetSymbolAddress((void**)&p_goh, g_goh);
    cudaGetSymbolAddress((void**)&p_gol, g_gol);
    cudaGetSymbolAddress((void**)&p_wlh, g_wlh);
    cudaGetSymbolAddress((void**)&p_wll, g_wll);
    cudaGetSymbolAddress((void**)&p_wrh, g_wrh);
    cudaGetSymbolAddress((void**)&p_wrl, g_wrl);
    cudaGetSymbolAddress((void**)&p_bsh, g_bsh);
    cudaGetSymbolAddress((void**)&p_bsl, g_bsl);
    cudaGetSymbolAddress((void**)&p_wlinh, g_wlinh);
    cudaGetSymbolAddress((void**)&p_wlinl, g_wlinl);

    cudaFuncSetAttribute(k_gemm_tc2, cudaFuncAttributeMaxDynamicSharedMemorySize, SMEM_BYTES2);

    const int T = 256;
    int edgeBlocks = (E + T - 1) / T;
    int nodeWarpBlocks = (N * 32 + T - 1) / T;

    // ---- CSR build ----
    k_zero_int<<<(N + T - 1) / T, T>>>(p_deg, N);
    k_count<<<edgeBlocks, T>>>(ei, E);
    k_scan<<<1, 1024>>>(N);
    k_csr_scatter<<<edgeBlocks, T>>>(ei, E);

    // ---- operand prep (independent) ----
    k_prep_x<<<(N * DF / 4 + T - 1) / T, T>>>(x, N * DF / 4);
    k_att_vec<<<2, T>>>(W_src, W_dst, att_s, att_d);
    k_prep_wT<<<(128 * 128 + T - 1) / T, T>>>(W_l, p_wlh, p_wll, 128, 128, 1.0f);
    k_prep_wT<<<(128 * 128 + T - 1) / T, T>>>(W_r, p_wrh, p_wrl, 128, 128, 1.0f);
    k_prep_bstack<<<(128 * 512 + T - 1) / T, T>>>(W_src);
    k_prep_wT<<<(64 * 128 + T - 1) / T, T>>>(W_lin, p_wlinh, p_wlinl, 128, 64, 1.0f);

    int gx = (N + TBM - 1) / TBM;

    // ---- SAGE:  h = relu(mean@W_l + x@W_r + b)  [fp32 out] ----
    k_sage_gather<<<nodeWarpBlocks, T>>>(x, N);
    dim3 g1(gx, DF / TBN);
    k_gemm_tc2<<<g1, 256, SMEM_BYTES2>>>(p_sxh, p_sxl, p_wlh, p_wll,
                                         p_xh, p_xl, p_wrh, p_wrl,
                                         b_sage, p_h, nullptr, nullptr,
                                         N, 128, DF, 1);

    // ---- GAT ----
    k_asd<<<nodeWarpBlocks, T>>>(N);
    k_gat_gather<<<nodeWarpBlocks, T>>>(N);
    k_gemm_tc2<<<g1, 256, SMEM_BYTES2>>>(p_ghh, p_ghl, p_bsh, p_bsl,
                                         nullptr, nullptr, nullptr, nullptr,
                                         b_gat, nullptr, p_goh, p_gol,
                                         N, 512, DF, 1);

    // ---- final linear ----
    dim3 g3(gx, 1);
    k_gemm_tc2<<<g3, 256, SMEM_BYTES2>>>(p_goh, p_gol, p_wlinh, p_wlinl,
                                         nullptr, nullptr, nullptr, nullptr,
                                         b_lin, out, nullptr, nullptr,
                                         N, 128, 64, 0);
}

// round 16
// speedup vs baseline: 1.4502x; 1.0618x over previous
#include <cuda_runtime.h>
#include <cuda_bf16.h>
#include <math.h>
#include <cstdint>

typedef unsigned int u32;

#define NN 50000
#define DF 128
#define HEADS 4
#define MAXE 800000

// ---------------- scratch (device globals; no allocations) ----------------
__device__ float g_h[NN * DF];              // SAGE output (fp32, for asd/gat_gather)
__device__ float g_as[NN * HEADS];
__device__ float g_ad[NN * HEADS];
__device__ float g_vs[DF * HEADS];
__device__ float g_vd[DF * HEADS];
__device__ int   g_deg[NN];
__device__ int   g_rowptr[NN + 1];
__device__ int   g_cursor[NN];
__device__ int   g_csrsrc[MAXE];
// bf16 hi/lo pair arrays (GEMM operands, K-major)
__device__ __nv_bfloat16 g_xh[NN * DF],  g_xl[NN * DF];
__device__ __nv_bfloat16 g_sxh[NN * DF], g_sxl[NN * DF];
__device__ __nv_bfloat16 g_ghh[NN * 512], g_ghl[NN * 512];
__device__ __nv_bfloat16 g_goh[NN * DF], g_gol[NN * DF];
__device__ __nv_bfloat16 g_wlh[128 * 128], g_wll[128 * 128];
__device__ __nv_bfloat16 g_wrh[128 * 128], g_wrl[128 * 128];
__device__ __nv_bfloat16 g_bsh[128 * 512], g_bsl[128 * 512];
__device__ __nv_bfloat16 g_wlinh[64 * 128], g_wlinl[64 * 128];

__device__ __forceinline__ float lrelu(float v) { return v > 0.f ? v : 0.2f * v; }

__device__ __forceinline__ u32 pack_bf(__nv_bfloat16 a, __nv_bfloat16 b) {
    return (u32)__bfloat16_as_ushort(a) | ((u32)__bfloat16_as_ushort(b) << 16);
}
__device__ __forceinline__ void store_pair4(__nv_bfloat16* dh, __nv_bfloat16* dl,
                                            size_t off, float4 v) {
    __nv_bfloat16 h0 = __float2bfloat16(v.x), h1 = __float2bfloat16(v.y);
    __nv_bfloat16 h2 = __float2bfloat16(v.z), h3 = __float2bfloat16(v.w);
    uint2 uh;
    uh.x = pack_bf(h0, h1);
    uh.y = pack_bf(h2, h3);
    __nv_bfloat16 l0 = __float2bfloat16(v.x - __bfloat162float(h0));
    __nv_bfloat16 l1 = __float2bfloat16(v.y - __bfloat162float(h1));
    __nv_bfloat16 l2 = __float2bfloat16(v.z - __bfloat162float(h2));
    __nv_bfloat16 l3 = __float2bfloat16(v.w - __bfloat162float(h3));
    uint2 ul;
    ul.x = pack_bf(l0, l1);
    ul.y = pack_bf(l2, l3);
    *(uint2*)(dh + off) = uh;
    *(uint2*)(dl + off) = ul;
}
__device__ __forceinline__ void store_pair1(__nv_bfloat16* dh, __nv_bfloat16* dl,
                                            size_t off, float v) {
    __nv_bfloat16 hi = __float2bfloat16(v);
    dh[off] = hi;
    dl[off] = __float2bfloat16(v - __bfloat162float(hi));
}

// ---------------- CSR build ----------------
__global__ void k_zero_int(int* p, int n) {
    int i = blockIdx.x * blockDim.x + threadIdx.x;
    if (i < n) p[i] = 0;
}
__global__ void k_count(const int* __restrict__ ei, int E) {
    int e = blockIdx.x * blockDim.x + threadIdx.x;
    if (e < E) atomicAdd(&g_deg[ei[E + e]], 1);
}
__global__ void k_scan(int N) {
    __shared__ int warpsums[32];
    int tid = threadIdx.x;
    int CH = (N + 1023) >> 10;
    int base = tid * CH;
    int s = 0;
    for (int i = 0; i < CH; i++) {
        int idx = base + i;
        if (idx < N) s += g_deg[idx];
    }
    int lane = tid & 31, wid = tid >> 5;
    int v = s;
    #pragma unroll
    for (int o = 1; o < 32; o <<= 1) {
        int t = __shfl_up_sync(0xffffffff, v, o);
        if (lane >= o) v += t;
    }
    if (lane == 31) warpsums[wid] = v;
    __syncthreads();
    if (wid == 0) {
        int w = warpsums[lane];
        #pragma unroll
        for (int o = 1; o < 32; o <<= 1) {
            int t = __shfl_up_sync(0xffffffff, w, o);
            if (lane >= o) w += t;
        }
        warpsums[lane] = w;
    }
    __syncthreads();
    int offset = v - s + (wid > 0 ? warpsums[wid - 1] : 0);
    for (int i = 0; i < CH; i++) {
        int idx = base + i;
        if (idx < N) {
            g_rowptr[idx] = offset;
            offset += g_deg[idx];
            g_cursor[idx] = 0;
        }
    }
    if (tid == 1023) g_rowptr[N] = offset;
}
__global__ void k_csr_scatter(const int* __restrict__ ei, int E) {
    int e = blockIdx.x * blockDim.x + threadIdx.x;
    if (e >= E) return;
    int s = ei[e], d = ei[E + e];
    int pos = atomicAdd(&g_cursor[d], 1);
    g_csrsrc[g_rowptr[d] + pos] = s;
}

// ---------------- fused operand prep (one kernel) ----------------
__global__ void k_prep_all(const float* __restrict__ x,
                           const float* __restrict__ W_l, const float* __restrict__ W_r,
                           const float* __restrict__ Wsrc, const float* __restrict__ Wdst,
                           const float* __restrict__ atts, const float* __restrict__ attd,
                           const float* __restrict__ W_lin, int n4x) {
    int i = blockIdx.x * blockDim.x + threadIdx.x;
    if (i < n4x) {                       // x -> pairs
        float4 v = ((const float4*)x)[i];
        store_pair4(g_xh, g_xl, (size_t)i * 4, v);
        return;
    }
    int j = i - n4x;
    if (j < 16384) {                     // W_l^T [n][k]
        int n = j >> 7, k = j & 127;
        store_pair1(g_wlh, g_wll, j, W_l[(size_t)k * 128 + n]);
        return;
    }
    j -= 16384;
    if (j < 16384) {                     // W_r^T [n][k]
        int n = j >> 7, k = j & 127;
        store_pair1(g_wrh, g_wrl, j, W_r[(size_t)k * 128 + n]);
        return;
    }
    j -= 16384;
    if (j < 65536) {                     // bstack [n][kk]: kk = h*128+k
        int n = j >> 9, kk = j & 511;
        int k = kk & 127, h = kk >> 7;
        store_pair1(g_bsh, g_bsl, j, 0.25f * Wsrc[(size_t)k * 512 + h * 128 + n]);
        return;
    }
    j -= 65536;
    if (j < 8192) {                      // W_lin^T [n][k], N=64,K=128
        int n = j >> 7, k = j & 127;
        store_pair1(g_wlinh, g_wlinl, j, W_lin[(size_t)k * 64 + n]);
        return;
    }
    j -= 8192;
    if (j < 512) {                       // att vectors
        int k = j >> 2, h = j & 3;
        float s = 0.f, d = 0.f;
        for (int c = 0; c < DF; c++) {
            s = fmaf(Wsrc[(size_t)k * 512 + h * 128 + c], atts[h * 128 + c], s);
            d = fmaf(Wdst[(size_t)k * 512 + h * 128 + c], attd[h * 128 + c], d);
        }
        g_vs[k * 4 + h] = s;
        g_vd[k * 4 + h] = d;
    }
}

// ---------------- SAGE mean gather: warp per node, chunked -> bf16 pairs ----------------
__global__ void k_sage_gather(const float* __restrict__ x, int N) {
    int gt = blockIdx.x * blockDim.x + threadIdx.x;
    int n = gt >> 5, lane = gt & 31;
    if (n >= N) return;
    int beg = g_rowptr[n], end = g_rowptr[n + 1];
    float4 acc = make_float4(0.f, 0.f, 0.f, 0.f);
    for (int b0 = beg; b0 < end; b0 += 32) {
        int i = b0 + lane;
        int idx = (i < end) ? g_csrsrc[i] : 0;
        int cnt = end - b0;
        if (cnt > 32) cnt = 32;
        for (int j = 0; j < cnt; j++) {
            int s = __shfl_sync(0xffffffffu, idx, j);
            float4 v = ((const float4*)(x + (size_t)s * DF))[lane];
            acc.x += v.x; acc.y += v.y; acc.z += v.z; acc.w += v.w;
        }
    }
    float inv = 1.f / fmaxf((float)(end - beg), 1.f);
    acc.x *= inv; acc.y *= inv; acc.z *= inv; acc.w *= inv;
    store_pair4(g_sxh, g_sxl, (size_t)n * DF + lane * 4, acc);
}

// ---------------- HMMA GEMM (pre-split pairs, cp.async 3-stage) ----------------
#define TBM 128
#define TBN 64
#define TBK 32
#define STG_BYTES 30720
#define OFF_AL2 10240
#define OFF_BH2 20480
#define OFF_BL2 25600
#define SMEM_BYTES3 (3 * STG_BYTES)

__device__ __forceinline__ u32 ld2bf(const __nv_bfloat16* p) {
    return *reinterpret_cast<const u32*>(p);
}
__device__ __forceinline__ void cp16(u32 dst, const void* src) {
    asm volatile("cp.async.cg.shared.global [%0], [%1], 16;" :: "r"(dst), "l"(src) : "memory");
}
#define CP_COMMIT() asm volatile("cp.async.commit_group;" ::: "memory")
#define CP_WAIT1()  asm volatile("cp.async.wait_group 1;" ::: "memory")

__device__ __forceinline__ void mma_bf16(float* d, const u32* a, u32 b0, u32 b1) {
    asm volatile(
        "mma.sync.aligned.m16n8k16.row.col.f32.bf16.bf16.f32 "
        "{%0,%1,%2,%3},{%4,%5,%6,%7},{%8,%9},{%0,%1,%2,%3};"
        : "+f"(d[0]), "+f"(d[1]), "+f"(d[2]), "+f"(d[3])
        : "r"(a[0]), "r"(a[1]), "r"(a[2]), "r"(a[3]), "r"(b0), "r"(b1));
}

__global__ __launch_bounds__(256) void k_gemm_tc3(
    const __nv_bfloat16* __restrict__ Ah1, const __nv_bfloat16* __restrict__ Al1,
    const __nv_bfloat16* __restrict__ Bh1, const __nv_bfloat16* __restrict__ Bl1,
    const __nv_bfloat16* __restrict__ Ah2, const __nv_bfloat16* __restrict__ Al2,
    const __nv_bfloat16* __restrict__ Bh2, const __nv_bfloat16* __restrict__ Bl2,
    const float* __restrict__ bias, float* __restrict__ Cf,
    __nv_bfloat16* __restrict__ Ch, __nv_bfloat16* __restrict__ Cl,
    int M, int Kin, int Ncols, int do_relu) {
    extern __shared__ char smc[];
    int tid = threadIdx.x;
    int w = tid >> 5, lane = tid & 31;
    int wm = w & 3, wn = w >> 2;       // 4 x 2 warp grid; warp tile 32x32
    int m0 = blockIdx.x * TBM, n0 = blockIdx.y * TBN;
    float acc[2][4][4] = {};
    int npairs = Ah2 ? 2 : 1;
    int ktiles = Kin >> 5;
    int total = npairs * ktiles;       // >= 4 always (Kin >= 128)

    int ar0 = (tid * 2) >> 2, ac0 = ((tid * 2) & 3) * 8;
    int ar1 = (tid * 2 + 1) >> 2, ac1 = ((tid * 2 + 1) & 3) * 8;
    int br = tid >> 2, bc = (tid & 3) * 8;
    // clamp A rows (out-of-range rows produce garbage only in masked outputs)
    int ga0 = m0 + ar0; if (ga0 >= M) ga0 = M - 1;
    int ga1 = m0 + ar1; if (ga1 >= M) ga1 = M - 1;
    size_t aoff0 = (size_t)ga0 * Kin + ac0;
    size_t aoff1 = (size_t)ga1 * Kin + ac1;
    size_t boff = (size_t)(n0 + br) * Kin + bc;
    u32 sa0 = (u32)(ar0 * 40 + ac0) * 2;
    u32 sa1 = (u32)(ar1 * 40 + ac1) * 2;
    u32 sbo = (u32)(br * 40 + bc) * 2;
    u32 smb = (u32)__cvta_generic_to_shared(smc);

    auto issue = [&](int stg, int t) {
        int p = t / ktiles;
        int k0 = (t - p * ktiles) * TBK;
        const __nv_bfloat16* Ah = p ? Ah2 : Ah1;
        const __nv_bfloat16* Al = p ? Al2 : Al1;
        const __nv_bfloat16* Bh = p ? Bh2 : Bh1;
        const __nv_bfloat16* Bl = p ? Bl2 : Bl1;
        u32 st = smb + stg * STG_BYTES;
        cp16(st + sa0, Ah + aoff0 + k0);
        cp16(st + sa1, Ah + aoff1 + k0);
        cp16(st + OFF_AL2 + sa0, Al + aoff0 + k0);
        cp16(st + OFF_AL2 + sa1, Al + aoff1 + k0);
        cp16(st + OFF_BH2 + sbo, Bh + boff + k0);
        cp16(st + OFF_BL2 + sbo, Bl + boff + k0);
    };
    issue(0, 0); CP_COMMIT();
    issue(1, 1); CP_COMMIT();

    for (int t = 0; t < total; t++) {
        CP_WAIT1();
        __syncthreads();
        // issue t+2 into the buffer freed by compute(t-1) (safe after the sync)
        if (t + 2 < total) issue((t + 2) % 3, t + 2);
        CP_COMMIT();

        char* cs = smc + (t % 3) * STG_BYTES;
        const __nv_bfloat16* cAh = (const __nv_bfloat16*)cs;
        const __nv_bfloat16* cAl = (const __nv_bfloat16*)(cs + OFF_AL2);
        const __nv_bfloat16* cBh = (const __nv_bfloat16*)(cs + OFF_BH2);
        const __nv_bfloat16* cBl = (const __nv_bfloat16*)(cs + OFF_BL2);
        #pragma unroll
        for (int kk = 0; kk < TBK; kk += 16) {
            int kc = kk + (lane & 3) * 2;
            int kc8 = kc + 8;
            u32 bhf[4][2];
            u32 blf[4][2];
            #pragma unroll
            for (int nt = 0; nt < 4; nt++) {
                int nc = wn * 32 + nt * 8 + (lane >> 2);
                bhf[nt][0] = ld2bf(&cBh[nc * 40 + kc]);
                bhf[nt][1] = ld2bf(&cBh[nc * 40 + kc8]);
                blf[nt][0] = ld2bf(&cBl[nc * 40 + kc]);
                blf[nt][1] = ld2bf(&cBl[nc * 40 + kc8]);
            }
            #pragma unroll
            for (int mt = 0; mt < 2; mt++) {
                int ar = wm * 32 + mt * 16 + (lane >> 2);
                int ar8 = ar + 8;
                u32 ah[4];
                u32 al[4];
                ah[0] = ld2bf(&cAh[ar * 40 + kc]);
                ah[1] = ld2bf(&cAh[ar8 * 40 + kc]);
                ah[2] = ld2bf(&cAh[ar * 40 + kc8]);
                ah[3] = ld2bf(&cAh[ar8 * 40 + kc8]);
                al[0] = ld2bf(&cAl[ar * 40 + kc]);
                al[1] = ld2bf(&cAl[ar8 * 40 + kc]);
                al[2] = ld2bf(&cAl[ar * 40 + kc8]);
                al[3] = ld2bf(&cAl[ar8 * 40 + kc8]);
                #pragma unroll
                for (int nt = 0; nt < 4; nt++) {
                    mma_bf16(acc[mt][nt], ah, bhf[nt][0], bhf[nt][1]);
                    mma_bf16(acc[mt][nt], ah, blf[nt][0], blf[nt][1]);
                    mma_bf16(acc[mt][nt], al, bhf[nt][0], bhf[nt][1]);
                }
            }
        }
        __syncthreads();
    }
    // epilogue
    #pragma unroll
    for (int mt = 0; mt < 2; mt++) {
        int r0 = m0 + wm * 32 + mt * 16 + (lane >> 2);
        #pragma unroll
        for (int nt = 0; nt < 4; nt++) {
            int c0 = n0 + wn * 32 + nt * 8 + (lane & 3) * 2;
            float2 v0 = make_float2(acc[mt][nt][0], acc[mt][nt][1]);
            float2 v1 = make_float2(acc[mt][nt][2], acc[mt][nt][3]);
            if (bias) {
                float2 bb = *(const float2*)(bias + c0);
                v0.x += bb.x; v0.y += bb.y;
                v1.x += bb.x; v1.y += bb.y;
            }
            if (do_relu) {
                v0.x = fmaxf(v0.x, 0.f); v0.y = fmaxf(v0.y, 0.f);
                v1.x = fmaxf(v1.x, 0.f); v1.y = fmaxf(v1.y, 0.f);
            }
            if (Cf) {
                if (r0 < M) *(float2*)(Cf + (size_t)r0 * Ncols + c0) = v0;
                if (r0 + 8 < M) *(float2*)(Cf + (size_t)(r0 + 8) * Ncols + c0) = v1;
            } else {
                if (r0 < M) {
                    size_t oo = (size_t)r0 * Ncols + c0;
                    __nv_bfloat16 h0 = __float2bfloat16(v0.x);
                    __nv_bfloat16 h1 = __float2bfloat16(v0.y);
                    *(u32*)(Ch + oo) = pack_bf(h0, h1);
                    *(u32*)(Cl + oo) = pack_bf(
                        __float2bfloat16(v0.x - __bfloat162float(h0)),
                        __float2bfloat16(v0.y - __bfloat162float(h1)));
                }
                if (r0 + 8 < M) {
                    size_t oo = (size_t)(r0 + 8) * Ncols + c0;
                    __nv_bfloat16 h0 = __float2bfloat16(v1.x);
                    __nv_bfloat16 h1 = __float2bfloat16(v1.y);
                    *(u32*)(Ch + oo) = pack_bf(h0, h1);
                    *(u32*)(Cl + oo) = pack_bf(
                        __float2bfloat16(v1.x - __bfloat162float(h0)),
                        __float2bfloat16(v1.y - __bfloat162float(h1)));
                }
            }
        }
    }
}

// ---------------- per-node a_s, a_d: warp per node ----------------
__global__ void k_asd(int N) {
    __shared__ float svs[DF * 4];
    __shared__ float svd[DF * 4];
    for (int i = threadIdx.x; i < DF * 4; i += blockDim.x) {
        svs[i] = g_vs[i];
        svd[i] = g_vd[i];
    }
    __syncthreads();
    int gt = blockIdx.x * blockDim.x + threadIdx.x;
    int n = gt >> 5, lane = gt & 31;
    if (n >= N) return;
    float as[4] = {}, ad[4] = {};
    #pragma unroll
    for (int kk = 0; kk < 4; kk++) {
        int k = lane + kk * 32;
        float hv = g_h[(size_t)n * DF + k];
        #pragma unroll
        for (int h = 0; h < 4; h++) {
            as[h] = fmaf(hv, svs[k * 4 + h], as[h]);
            ad[h] = fmaf(hv, svd[k * 4 + h], ad[h]);
        }
    }
    #pragma unroll
    for (int h = 0; h < 4; h++) {
        #pragma unroll
        for (int off = 16; off > 0; off >>= 1) {
            as[h] += __shfl_down_sync(0xffffffff, as[h], off);
            ad[h] += __shfl_down_sync(0xffffffff, ad[h], off);
        }
    }
    if (lane == 0) {
        #pragma unroll
        for (int h = 0; h < 4; h++) {
            g_as[n * 4 + h] = as[h];
            g_ad[n * 4 + h] = ad[h];
        }
    }
}

// ---------------- fused GAT softmax + aggregation -> bf16 pairs ----------------
__global__ void k_gat_gather(int N) {
    int gt = blockIdx.x * blockDim.x + threadIdx.x;
    int n = gt >> 5, lane = gt & 31;
    if (n >= N) return;
    int beg = g_rowptr[n], end = g_rowptr[n + 1];
    float4 ad = *(const float4*)(g_ad + (size_t)n * 4);

    float4 m = make_float4(-INFINITY, -INFINITY, -INFINITY, -INFINITY);
    for (int i = beg + lane; i < end; i += 32) {
        int s = g_csrsrc[i];
        float4 as = *(const float4*)(g_as + (size_t)s * 4);
        m.x = fmaxf(m.x, lrelu(as.x + ad.x));
        m.y = fmaxf(m.y, lrelu(as.y + ad.y));
        m.z = fmaxf(m.z, lrelu(as.z + ad.z));
        m.w = fmaxf(m.w, lrelu(as.w + ad.w));
    }
    #pragma unroll
    for (int o = 16; o > 0; o >>= 1) {
        m.x = fmaxf(m.x, __shfl_xor_sync(0xffffffff, m.x, o));
        m.y = fmaxf(m.y, __shfl_xor_sync(0xffffffff, m.y, o));
        m.z = fmaxf(m.z, __shfl_xor_sync(0xffffffff, m.z, o));
        m.w = fmaxf(m.w, __shfl_xor_sync(0xffffffff, m.w, o));
    }

    float4 denl = make_float4(0.f, 0.f, 0.f, 0.f);
    float4 a0 = make_float4(0.f, 0.f, 0.f, 0.f);
    float4 a1 = a0, a2 = a0, a3 = a0;
    for (int b0 = beg; b0 < end; b0 += 32) {
        int i = b0 + lane;
        int idx = 0;
        float4 wv = make_float4(0.f, 0.f, 0.f, 0.f);
        if (i < end) {
            idx = g_csrsrc[i];
            float4 as = *(const float4*)(g_as + (size_t)idx * 4);
            wv.x = __expf(lrelu(as.x + ad.x) - m.x);
            wv.y = __expf(lrelu(as.y + ad.y) - m.y);
            wv.z = __expf(lrelu(as.z + ad.z) - m.z);
            wv.w = __expf(lrelu(as.w + ad.w) - m.w);
            denl.x += wv.x; denl.y += wv.y; denl.z += wv.z; denl.w += wv.w;
        }
        int cnt = end - b0;
        if (cnt > 32) cnt = 32;
        for (int j = 0; j < cnt; j++) {
            int s = __shfl_sync(0xffffffffu, idx, j);
            float wx = __shfl_sync(0xffffffffu, wv.x, j);
            float wy = __shfl_sync(0xffffffffu, wv.y, j);
            float wz = __shfl_sync(0xffffffffu, wv.z, j);
            float ww = __shfl_sync(0xffffffffu, wv.w, j);
            float4 hv = ((const float4*)(g_h + (size_t)s * DF))[lane];
            a0.x = fmaf(hv.x, wx, a0.x); a0.y = fmaf(hv.y, wx, a0.y);
            a0.z = fmaf(hv.z, wx, a0.z); a0.w = fmaf(hv.w, wx, a0.w);
            a1.x = fmaf(hv.x, wy, a1.x); a1.y = fmaf(hv.y, wy, a1.y);
            a1.z = fmaf(hv.z, wy, a1.z); a1.w = fmaf(hv.w, wy, a1.w);
            a2.x = fmaf(hv.x, wz, a2.x); a2.y = fmaf(hv.y, wz, a2.y);
            a2.z = fmaf(hv.z, wz, a2.z); a2.w = fmaf(hv.w, wz, a2.w);
            a3.x = fmaf(hv.x, ww, a3.x); a3.y = fmaf(hv.y, ww, a3.y);
            a3.z = fmaf(hv.z, ww, a3.z); a3.w = fmaf(hv.w, ww, a3.w);
        }
    }
    #pragma unroll
    for (int o = 16; o > 0; o >>= 1) {
        denl.x += __shfl_xor_sync(0xffffffff, denl.x, o);
        denl.y += __shfl_xor_sync(0xffffffff, denl.y, o);
        denl.z += __shfl_xor_sync(0xffffffff, denl.z, o);
        denl.w += __shfl_xor_sync(0xffffffff, denl.w, o);
    }
    float i0 = denl.x > 0.f ? 1.f / denl.x : 0.f;
    float i1 = denl.y > 0.f ? 1.f / denl.y : 0.f;
    float i2 = denl.z > 0.f ? 1.f / denl.z : 0.f;
    float i3 = denl.w > 0.f ? 1.f / denl.w : 0.f;
    a0.x *= i0; a0.y *= i0; a0.z *= i0; a0.w *= i0;
    a1.x *= i1; a1.y *= i1; a1.z *= i1; a1.w *= i1;
    a2.x *= i2; a2.y *= i2; a2.z *= i2; a2.w *= i2;
    a3.x *= i3; a3.y *= i3; a3.z *= i3; a3.w *= i3;
    size_t ob = (size_t)n * 512 + lane * 4;
    store_pair4(g_ghh, g_ghl, ob + 0 * 128, a0);
    store_pair4(g_ghh, g_ghl, ob + 1 * 128, a1);
    store_pair4(g_ghh, g_ghl, ob + 2 * 128, a2);
    store_pair4(g_ghh, g_ghl, ob + 3 * 128, a3);
}

// ---------------- launch ----------------
extern "C" void kernel_launch(void* const* d_in, const int* in_sizes, int n_in,
                              void* d_out, int out_size) {
    const float* x      = (const float*)d_in[0];
    const int*   ei     = (const int*)d_in[1];
    const float* W_l    = (const float*)d_in[2];
    const float* W_r    = (const float*)d_in[3];
    const float* b_sage = (const float*)d_in[4];
    const float* W_src  = (const float*)d_in[5];
    const float* W_dst  = (const float*)d_in[6];
    const float* att_s  = (const float*)d_in[7];
    const float* att_d  = (const float*)d_in[8];
    const float* b_gat  = (const float*)d_in[9];
    const float* W_lin  = (const float*)d_in[10];
    const float* b_lin  = (const float*)d_in[11];
    float* out = (float*)d_out;

    int N = in_sizes[0] / DF;
    int E = in_sizes[1] / 2;

    float* p_h;
    int* p_deg;
    __nv_bfloat16 *p_xh, *p_xl, *p_sxh, *p_sxl, *p_ghh, *p_ghl, *p_goh, *p_gol;
    __nv_bfloat16 *p_wlh, *p_wll, *p_wrh, *p_wrl, *p_bsh, *p_bsl, *p_wlinh, *p_wlinl;
    cudaGetSymbolAddress((void**)&p_h, g_h);
    cudaGetSymbolAddress((void**)&p_deg, g_deg);
    cudaGetSymbolAddress((void**)&p_xh, g_xh);
    cudaGetSymbolAddress((void**)&p_xl, g_xl);
    cudaGetSymbolAddress((void**)&p_sxh, g_sxh);
    cudaGetSymbolAddress((void**)&p_sxl, g_sxl);
    cudaGetSymbolAddress((void**)&p_ghh, g_ghh);
    cudaGetSymbolAddress((void**)&p_ghl, g_ghl);
    cudaGetSymbolAddress((void**)&p_goh, g_goh);
    cudaGetSymbolAddress((void**)&p_gol, g_gol);
    cudaGetSymbolAddress((void**)&p_wlh, g_wlh);
    cudaGetSymbolAddress((void**)&p_wll, g_wll);
    cudaGetSymbolAddress((void**)&p_wrh, g_wrh);
    cudaGetSymbolAddress((void**)&p_wrl, g_wrl);
    cudaGetSymbolAddress((void**)&p_bsh, g_bsh);
    cudaGetSymbolAddress((void**)&p_bsl, g_bsl);
    cudaGetSymbolAddress((void**)&p_wlinh, g_wlinh);
    cudaGetSymbolAddress((void**)&p_wlinl, g_wlinl);

    cudaFuncSetAttribute(k_gemm_tc3, cudaFuncAttributeMaxDynamicSharedMemorySize, SMEM_BYTES3);

    const int T = 256;
    int edgeBlocks = (E + T - 1) / T;
    int nodeWarpBlocks = (N * 32 + T - 1) / T;

    // ---- CSR build ----
    k_zero_int<<<(N + T - 1) / T, T>>>(p_deg, N);
    k_count<<<edgeBlocks, T>>>(ei, E);
    k_scan<<<1, 1024>>>(N);
    k_csr_scatter<<<edgeBlocks, T>>>(ei, E);

    // ---- fused operand prep ----
    int n4x = N * DF / 4;
    int prep_total = n4x + 16384 + 16384 + 65536 + 8192 + 512;
    k_prep_all<<<(prep_total + T - 1) / T, T>>>(x, W_l, W_r, W_src, W_dst,
                                                att_s, att_d, W_lin, n4x);

    int gx = (N + TBM - 1) / TBM;

    // ---- SAGE:  h = relu(mean@W_l + x@W_r + b)  [fp32 out] ----
    k_sage_gather<<<nodeWarpBlocks, T>>>(x, N);
    dim3 g1(gx, DF / TBN);
    k_gemm_tc3<<<g1, 256, SMEM_BYTES3>>>(p_sxh, p_sxl, p_wlh, p_wll,
                                         p_xh, p_xl, p_wrh, p_wrl,
                                         b_sage, p_h, nullptr, nullptr,
                                         N, 128, DF, 1);

    // ---- GAT ----
    k_asd<<<nodeWarpBlocks, T>>>(N);
    k_gat_gather<<<nodeWarpBlocks, T>>>(N);
    k_gemm_tc3<<<g1, 256, SMEM_BYTES3>>>(p_ghh, p_ghl, p_bsh, p_bsl,
                                         nullptr, nullptr, nullptr, nullptr,
                                         b_gat, nullptr, p_goh, p_gol,
                                         N, 512, DF, 1);

    // ---- final linear ----
    dim3 g3(gx, 1);
    k_gemm_tc3<<<g3, 256, SMEM_BYTES3>>>(p_goh, p_gol, p_wlinh, p_wlinl,
                                         nullptr, nullptr, nullptr, nullptr,
                                         b_lin, out, nullptr, nullptr,
                                         N, 128, 64, 0);
}

// round 17
// speedup vs baseline: 1.4798x; 1.0204x over previous
#include <cuda_runtime.h>
#include <cuda_bf16.h>
#include <math.h>
#include <cstdint>

typedef unsigned int u32;

#define NN 50000
#define DF 128
#define HEADS 4
#define MAXE 800000

// ---------------- scratch (device globals; no allocations) ----------------
__device__ float g_h[NN * DF];              // SAGE output (fp32, for asd/gat_gather)
__device__ float g_as[NN * HEADS];
__device__ float g_ad[NN * HEADS];
__device__ float g_vs[DF * HEADS];
__device__ float g_vd[DF * HEADS];
__device__ int   g_deg[NN];
__device__ int   g_rowptr[NN + 1];
__device__ int   g_cursor[NN];
__device__ int   g_csrsrc[MAXE];
// bf16 hi/lo pair arrays (GEMM operands, K-major)
__device__ __nv_bfloat16 g_xh[NN * DF],  g_xl[NN * DF];
__device__ __nv_bfloat16 g_sxh[NN * DF], g_sxl[NN * DF];
__device__ __nv_bfloat16 g_ghh[NN * 512], g_ghl[NN * 512];
__device__ __nv_bfloat16 g_goh[NN * DF], g_gol[NN * DF];
__device__ __nv_bfloat16 g_wlh[128 * 128], g_wll[128 * 128];
__device__ __nv_bfloat16 g_wrh[128 * 128], g_wrl[128 * 128];
__device__ __nv_bfloat16 g_bsh[128 * 512], g_bsl[128 * 512];
__device__ __nv_bfloat16 g_wlinh[64 * 128], g_wlinl[64 * 128];

__device__ __forceinline__ float lrelu(float v) { return v > 0.f ? v : 0.2f * v; }

__device__ __forceinline__ u32 pack_bf(__nv_bfloat16 a, __nv_bfloat16 b) {
    return (u32)__bfloat16_as_ushort(a) | ((u32)__bfloat16_as_ushort(b) << 16);
}
__device__ __forceinline__ void store_pair4(__nv_bfloat16* dh, __nv_bfloat16* dl,
                                            size_t off, float4 v) {
    __nv_bfloat16 h0 = __float2bfloat16(v.x), h1 = __float2bfloat16(v.y);
    __nv_bfloat16 h2 = __float2bfloat16(v.z), h3 = __float2bfloat16(v.w);
    uint2 uh;
    uh.x = pack_bf(h0, h1);
    uh.y = pack_bf(h2, h3);
    __nv_bfloat16 l0 = __float2bfloat16(v.x - __bfloat162float(h0));
    __nv_bfloat16 l1 = __float2bfloat16(v.y - __bfloat162float(h1));
    __nv_bfloat16 l2 = __float2bfloat16(v.z - __bfloat162float(h2));
    __nv_bfloat16 l3 = __float2bfloat16(v.w - __bfloat162float(h3));
    uint2 ul;
    ul.x = pack_bf(l0, l1);
    ul.y = pack_bf(l2, l3);
    *(uint2*)(dh + off) = uh;
    *(uint2*)(dl + off) = ul;
}
__device__ __forceinline__ void store_pair1(__nv_bfloat16* dh, __nv_bfloat16* dl,
                                            size_t off, float v) {
    __nv_bfloat16 hi = __float2bfloat16(v);
    dh[off] = hi;
    dl[off] = __float2bfloat16(v - __bfloat162float(hi));
}

// ---------------- CSR build ----------------
__global__ void k_zero_int(int* p, int n) {
    int i = blockIdx.x * blockDim.x + threadIdx.x;
    if (i < n) p[i] = 0;
}
__global__ void k_count(const int* __restrict__ ei, int E) {
    int e = blockIdx.x * blockDim.x + threadIdx.x;
    if (e < E) atomicAdd(&g_deg[ei[E + e]], 1);
}
__global__ void k_scan(int N) {
    __shared__ int warpsums[32];
    int tid = threadIdx.x;
    int CH = (N + 1023) >> 10;
    int base = tid * CH;
    int s = 0;
    for (int i = 0; i < CH; i++) {
        int idx = base + i;
        if (idx < N) s += g_deg[idx];
    }
    int lane = tid & 31, wid = tid >> 5;
    int v = s;
    #pragma unroll
    for (int o = 1; o < 32; o <<= 1) {
        int t = __shfl_up_sync(0xffffffff, v, o);
        if (lane >= o) v += t;
    }
    if (lane == 31) warpsums[wid] = v;
    __syncthreads();
    if (wid == 0) {
        int w = warpsums[lane];
        #pragma unroll
        for (int o = 1; o < 32; o <<= 1) {
            int t = __shfl_up_sync(0xffffffff, w, o);
            if (lane >= o) w += t;
        }
        warpsums[lane] = w;
    }
    __syncthreads();
    int offset = v - s + (wid > 0 ? warpsums[wid - 1] : 0);
    for (int i = 0; i < CH; i++) {
        int idx = base + i;
        if (idx < N) {
            g_rowptr[idx] = offset;
            offset += g_deg[idx];
            g_cursor[idx] = 0;
        }
    }
    if (tid == 1023) g_rowptr[N] = offset;
}
__global__ void k_csr_scatter(const int* __restrict__ ei, int E) {
    int e = blockIdx.x * blockDim.x + threadIdx.x;
    if (e >= E) return;
    int s = ei[e], d = ei[E + e];
    int pos = atomicAdd(&g_cursor[d], 1);
    g_csrsrc[g_rowptr[d] + pos] = s;
}

// ---------------- fused operand prep (one kernel) ----------------
__global__ void k_prep_all(const float* __restrict__ x,
                           const float* __restrict__ W_l, const float* __restrict__ W_r,
                           const float* __restrict__ Wsrc, const float* __restrict__ Wdst,
                           const float* __restrict__ atts, const float* __restrict__ attd,
                           const float* __restrict__ W_lin, int n4x) {
    int i = blockIdx.x * blockDim.x + threadIdx.x;
    if (i < n4x) {
        float4 v = ((const float4*)x)[i];
        store_pair4(g_xh, g_xl, (size_t)i * 4, v);
        return;
    }
    int j = i - n4x;
    if (j < 16384) {
        int n = j >> 7, k = j & 127;
        store_pair1(g_wlh, g_wll, j, W_l[(size_t)k * 128 + n]);
        return;
    }
    j -= 16384;
    if (j < 16384) {
        int n = j >> 7, k = j & 127;
        store_pair1(g_wrh, g_wrl, j, W_r[(size_t)k * 128 + n]);
        return;
    }
    j -= 16384;
    if (j < 65536) {
        int n = j >> 9, kk = j & 511;
        int k = kk & 127, h = kk >> 7;
        store_pair1(g_bsh, g_bsl, j, 0.25f * Wsrc[(size_t)k * 512 + h * 128 + n]);
        return;
    }
    j -= 65536;
    if (j < 8192) {
        int n = j >> 7, k = j & 127;
        store_pair1(g_wlinh, g_wlinl, j, W_lin[(size_t)k * 64 + n]);
        return;
    }
    j -= 8192;
    if (j < 512) {
        int k = j >> 2, h = j & 3;
        float s = 0.f, d = 0.f;
        for (int c = 0; c < DF; c++) {
            s = fmaf(Wsrc[(size_t)k * 512 + h * 128 + c], atts[h * 128 + c], s);
            d = fmaf(Wdst[(size_t)k * 512 + h * 128 + c], attd[h * 128 + c], d);
        }
        g_vs[k * 4 + h] = s;
        g_vd[k * 4 + h] = d;
    }
}

// ---------------- SAGE mean gather: warp per node, smem-staged indices ----------------
__global__ void k_sage_gather(const float* __restrict__ x, int N) {
    __shared__ int sidx[8][32];
    int gt = blockIdx.x * blockDim.x + threadIdx.x;
    int n = gt >> 5, lane = gt & 31;
    int wd = (threadIdx.x >> 5);
    if (n >= N) return;
    int beg = g_rowptr[n], end = g_rowptr[n + 1];
    float4 acc = make_float4(0.f, 0.f, 0.f, 0.f);
    for (int b0 = beg; b0 < end; b0 += 32) {
        int i = b0 + lane;
        sidx[wd][lane] = (i < end) ? g_csrsrc[i] : 0;
        __syncwarp();
        int cnt = end - b0;
        if (cnt > 32) cnt = 32;
        for (int j = 0; j < cnt; j++) {
            int s = sidx[wd][j];
            float4 v = ((const float4*)(x + (size_t)s * DF))[lane];
            acc.x += v.x; acc.y += v.y; acc.z += v.z; acc.w += v.w;
        }
        __syncwarp();
    }
    float inv = 1.f / fmaxf((float)(end - beg), 1.f);
    acc.x *= inv; acc.y *= inv; acc.z *= inv; acc.w *= inv;
    store_pair4(g_sxh, g_sxl, (size_t)n * DF + lane * 4, acc);
}

// ---------------- HMMA GEMM (pre-split pairs, cp.async 3-stage) ----------------
#define TBM 128
#define TBN 64
#define TBK 32
#define STG_BYTES 30720
#define OFF_AL2 10240
#define OFF_BH2 20480
#define OFF_BL2 25600
#define SMEM_BYTES3 (3 * STG_BYTES)

__device__ __forceinline__ u32 ld2bf(const __nv_bfloat16* p) {
    return *reinterpret_cast<const u32*>(p);
}
__device__ __forceinline__ void cp16(u32 dst, const void* src) {
    asm volatile("cp.async.cg.shared.global [%0], [%1], 16;" :: "r"(dst), "l"(src) : "memory");
}
#define CP_COMMIT() asm volatile("cp.async.commit_group;" ::: "memory")
#define CP_WAIT1()  asm volatile("cp.async.wait_group 1;" ::: "memory")

__device__ __forceinline__ void mma_bf16(float* d, const u32* a, u32 b0, u32 b1) {
    asm volatile(
        "mma.sync.aligned.m16n8k16.row.col.f32.bf16.bf16.f32 "
        "{%0,%1,%2,%3},{%4,%5,%6,%7},{%8,%9},{%0,%1,%2,%3};"
        : "+f"(d[0]), "+f"(d[1]), "+f"(d[2]), "+f"(d[3])
        : "r"(a[0]), "r"(a[1]), "r"(a[2]), "r"(a[3]), "r"(b0), "r"(b1));
}

__global__ __launch_bounds__(256) void k_gemm_tc3(
    const __nv_bfloat16* __restrict__ Ah1, const __nv_bfloat16* __restrict__ Al1,
    const __nv_bfloat16* __restrict__ Bh1, const __nv_bfloat16* __restrict__ Bl1,
    const __nv_bfloat16* __restrict__ Ah2, const __nv_bfloat16* __restrict__ Al2,
    const __nv_bfloat16* __restrict__ Bh2, const __nv_bfloat16* __restrict__ Bl2,
    const float* __restrict__ bias, float* __restrict__ Cf,
    __nv_bfloat16* __restrict__ Ch, __nv_bfloat16* __restrict__ Cl,
    int M, int Kin, int Ncols, int do_relu) {
    extern __shared__ char smc[];
    int tid = threadIdx.x;
    int w = tid >> 5, lane = tid & 31;
    int wm = w & 3, wn = w >> 2;
    int m0 = blockIdx.x * TBM, n0 = blockIdx.y * TBN;
    float acc[2][4][4] = {};
    int npairs = Ah2 ? 2 : 1;
    int ktiles = Kin >> 5;
    int total = npairs * ktiles;

    int ar0 = (tid * 2) >> 2, ac0 = ((tid * 2) & 3) * 8;
    int ar1 = (tid * 2 + 1) >> 2, ac1 = ((tid * 2 + 1) & 3) * 8;
    int br = tid >> 2, bc = (tid & 3) * 8;
    int ga0 = m0 + ar0; if (ga0 >= M) ga0 = M - 1;
    int ga1 = m0 + ar1; if (ga1 >= M) ga1 = M - 1;
    size_t aoff0 = (size_t)ga0 * Kin + ac0;
    size_t aoff1 = (size_t)ga1 * Kin + ac1;
    size_t boff = (size_t)(n0 + br) * Kin + bc;
    u32 sa0 = (u32)(ar0 * 40 + ac0) * 2;
    u32 sa1 = (u32)(ar1 * 40 + ac1) * 2;
    u32 sbo = (u32)(br * 40 + bc) * 2;
    u32 smb = (u32)__cvta_generic_to_shared(smc);

    auto issue = [&](int stg, int t) {
        int p = t / ktiles;
        int k0 = (t - p * ktiles) * TBK;
        const __nv_bfloat16* Ah = p ? Ah2 : Ah1;
        const __nv_bfloat16* Al = p ? Al2 : Al1;
        const __nv_bfloat16* Bh = p ? Bh2 : Bh1;
        const __nv_bfloat16* Bl = p ? Bl2 : Bl1;
        u32 st = smb + stg * STG_BYTES;
        cp16(st + sa0, Ah + aoff0 + k0);
        cp16(st + sa1, Ah + aoff1 + k0);
        cp16(st + OFF_AL2 + sa0, Al + aoff0 + k0);
        cp16(st + OFF_AL2 + sa1, Al + aoff1 + k0);
        cp16(st + OFF_BH2 + sbo, Bh + boff + k0);
        cp16(st + OFF_BL2 + sbo, Bl + boff + k0);
    };
    issue(0, 0); CP_COMMIT();
    issue(1, 1); CP_COMMIT();

    for (int t = 0; t < total; t++) {
        CP_WAIT1();
        __syncthreads();
        if (t + 2 < total) issue((t + 2) % 3, t + 2);
        CP_COMMIT();

        char* cs = smc + (t % 3) * STG_BYTES;
        const __nv_bfloat16* cAh = (const __nv_bfloat16*)cs;
        const __nv_bfloat16* cAl = (const __nv_bfloat16*)(cs + OFF_AL2);
        const __nv_bfloat16* cBh = (const __nv_bfloat16*)(cs + OFF_BH2);
        const __nv_bfloat16* cBl = (const __nv_bfloat16*)(cs + OFF_BL2);
        #pragma unroll
        for (int kk = 0; kk < TBK; kk += 16) {
            int kc = kk + (lane & 3) * 2;
            int kc8 = kc + 8;
            u32 bhf[4][2];
            u32 blf[4][2];
            #pragma unroll
            for (int nt = 0; nt < 4; nt++) {
                int nc = wn * 32 + nt * 8 + (lane >> 2);
                bhf[nt][0] = ld2bf(&cBh[nc * 40 + kc]);
                bhf[nt][1] = ld2bf(&cBh[nc * 40 + kc8]);
                blf[nt][0] = ld2bf(&cBl[nc * 40 + kc]);
                blf[nt][1] = ld2bf(&cBl[nc * 40 + kc8]);
            }
            #pragma unroll
            for (int mt = 0; mt < 2; mt++) {
                int ar = wm * 32 + mt * 16 + (lane >> 2);
                int ar8 = ar + 8;
                u32 ah[4];
                u32 al[4];
                ah[0] = ld2bf(&cAh[ar * 40 + kc]);
                ah[1] = ld2bf(&cAh[ar8 * 40 + kc]);
                ah[2] = ld2bf(&cAh[ar * 40 + kc8]);
                ah[3] = ld2bf(&cAh[ar8 * 40 + kc8]);
                al[0] = ld2bf(&cAl[ar * 40 + kc]);
                al[1] = ld2bf(&cAl[ar8 * 40 + kc]);
                al[2] = ld2bf(&cAl[ar * 40 + kc8]);
                al[3] = ld2bf(&cAl[ar8 * 40 + kc8]);
                #pragma unroll
                for (int nt = 0; nt < 4; nt++) {
                    mma_bf16(acc[mt][nt], ah, bhf[nt][0], bhf[nt][1]);
                    mma_bf16(acc[mt][nt], ah, blf[nt][0], blf[nt][1]);
                    mma_bf16(acc[mt][nt], al, bhf[nt][0], bhf[nt][1]);
                }
            }
        }
        __syncthreads();
    }
    // epilogue
    #pragma unroll
    for (int mt = 0; mt < 2; mt++) {
        int r0 = m0 + wm * 32 + mt * 16 + (lane >> 2);
        #pragma unroll
        for (int nt = 0; nt < 4; nt++) {
            int c0 = n0 + wn * 32 + nt * 8 + (lane & 3) * 2;
            float2 v0 = make_float2(acc[mt][nt][0], acc[mt][nt][1]);
            float2 v1 = make_float2(acc[mt][nt][2], acc[mt][nt][3]);
            if (bias) {
                float2 bb = *(const float2*)(bias + c0);
                v0.x += bb.x; v0.y += bb.y;
                v1.x += bb.x; v1.y += bb.y;
            }
            if (do_relu) {
                v0.x = fmaxf(v0.x, 0.f); v0.y = fmaxf(v0.y, 0.f);
                v1.x = fmaxf(v1.x, 0.f); v1.y = fmaxf(v1.y, 0.f);
            }
            if (Cf) {
                if (r0 < M) *(float2*)(Cf + (size_t)r0 * Ncols + c0) = v0;
                if (r0 + 8 < M) *(float2*)(Cf + (size_t)(r0 + 8) * Ncols + c0) = v1;
            } else {
                if (r0 < M) {
                    size_t oo = (size_t)r0 * Ncols + c0;
                    __nv_bfloat16 h0 = __float2bfloat16(v0.x);
                    __nv_bfloat16 h1 = __float2bfloat16(v0.y);
                    *(u32*)(Ch + oo) = pack_bf(h0, h1);
                    *(u32*)(Cl + oo) = pack_bf(
                        __float2bfloat16(v0.x - __bfloat162float(h0)),
                        __float2bfloat16(v0.y - __bfloat162float(h1)));
                }
                if (r0 + 8 < M) {
                    size_t oo = (size_t)(r0 + 8) * Ncols + c0;
                    __nv_bfloat16 h0 = __float2bfloat16(v1.x);
                    __nv_bfloat16 h1 = __float2bfloat16(v1.y);
                    *(u32*)(Ch + oo) = pack_bf(h0, h1);
                    *(u32*)(Cl + oo) = pack_bf(
                        __float2bfloat16(v1.x - __bfloat162float(h0)),
                        __float2bfloat16(v1.y - __bfloat162float(h1)));
                }
            }
        }
    }
}

// ---------------- per-node a_s, a_d: warp per node ----------------
__global__ void k_asd(int N) {
    __shared__ float svs[DF * 4];
    __shared__ float svd[DF * 4];
    for (int i = threadIdx.x; i < DF * 4; i += blockDim.x) {
        svs[i] = g_vs[i];
        svd[i] = g_vd[i];
    }
    __syncthreads();
    int gt = blockIdx.x * blockDim.x + threadIdx.x;
    int n = gt >> 5, lane = gt & 31;
    if (n >= N) return;
    float as[4] = {}, ad[4] = {};
    #pragma unroll
    for (int kk = 0; kk < 4; kk++) {
        int k = lane + kk * 32;
        float hv = g_h[(size_t)n * DF + k];
        #pragma unroll
        for (int h = 0; h < 4; h++) {
            as[h] = fmaf(hv, svs[k * 4 + h], as[h]);
            ad[h] = fmaf(hv, svd[k * 4 + h], ad[h]);
        }
    }
    #pragma unroll
    for (int h = 0; h < 4; h++) {
        #pragma unroll
        for (int off = 16; off > 0; off >>= 1) {
            as[h] += __shfl_down_sync(0xffffffff, as[h], off);
            ad[h] += __shfl_down_sync(0xffffffff, ad[h], off);
        }
    }
    if (lane == 0) {
        #pragma unroll
        for (int h = 0; h < 4; h++) {
            g_as[n * 4 + h] = as[h];
            g_ad[n * 4 + h] = ad[h];
        }
    }
}

// ---------------- fused GAT softmax + aggregation: smem-staged, -> bf16 pairs ----------------
__global__ void k_gat_gather(int N) {
    __shared__ int sidx[8][32];
    __shared__ float4 swv[8][32];
    int gt = blockIdx.x * blockDim.x + threadIdx.x;
    int n = gt >> 5, lane = gt & 31;
    int wd = (threadIdx.x >> 5);
    if (n >= N) return;
    int beg = g_rowptr[n], end = g_rowptr[n + 1];
    float4 ad = *(const float4*)(g_ad + (size_t)n * 4);

    float4 m = make_float4(-INFINITY, -INFINITY, -INFINITY, -INFINITY);
    for (int i = beg + lane; i < end; i += 32) {
        int s = g_csrsrc[i];
        float4 as = *(const float4*)(g_as + (size_t)s * 4);
        m.x = fmaxf(m.x, lrelu(as.x + ad.x));
        m.y = fmaxf(m.y, lrelu(as.y + ad.y));
        m.z = fmaxf(m.z, lrelu(as.z + ad.z));
        m.w = fmaxf(m.w, lrelu(as.w + ad.w));
    }
    #pragma unroll
    for (int o = 16; o > 0; o >>= 1) {
        m.x = fmaxf(m.x, __shfl_xor_sync(0xffffffff, m.x, o));
        m.y = fmaxf(m.y, __shfl_xor_sync(0xffffffff, m.y, o));
        m.z = fmaxf(m.z, __shfl_xor_sync(0xffffffff, m.z, o));
        m.w = fmaxf(m.w, __shfl_xor_sync(0xffffffff, m.w, o));
    }

    float4 denl = make_float4(0.f, 0.f, 0.f, 0.f);
    float4 a0 = make_float4(0.f, 0.f, 0.f, 0.f);
    float4 a1 = a0, a2 = a0, a3 = a0;
    for (int b0 = beg; b0 < end; b0 += 32) {
        int i = b0 + lane;
        int idx = 0;
        float4 wv = make_float4(0.f, 0.f, 0.f, 0.f);
        if (i < end) {
            idx = g_csrsrc[i];
            float4 as = *(const float4*)(g_as + (size_t)idx * 4);
            wv.x = __expf(lrelu(as.x + ad.x) - m.x);
            wv.y = __expf(lrelu(as.y + ad.y) - m.y);
            wv.z = __expf(lrelu(as.z + ad.z) - m.z);
            wv.w = __expf(lrelu(as.w + ad.w) - m.w);
            denl.x += wv.x; denl.y += wv.y; denl.z += wv.z; denl.w += wv.w;
        }
        sidx[wd][lane] = idx;
        swv[wd][lane] = wv;
        __syncwarp();
        int cnt = end - b0;
        if (cnt > 32) cnt = 32;
        for (int j = 0; j < cnt; j++) {
            int s = sidx[wd][j];
            float4 wj = swv[wd][j];
            float4 hv = ((const float4*)(g_h + (size_t)s * DF))[lane];
            a0.x = fmaf(hv.x, wj.x, a0.x); a0.y = fmaf(hv.y, wj.x, a0.y);
            a0.z = fmaf(hv.z, wj.x, a0.z); a0.w = fmaf(hv.w, wj.x, a0.w);
            a1.x = fmaf(hv.x, wj.y, a1.x); a1.y = fmaf(hv.y, wj.y, a1.y);
            a1.z = fmaf(hv.z, wj.y, a1.z); a1.w = fmaf(hv.w, wj.y, a1.w);
            a2.x = fmaf(hv.x, wj.z, a2.x); a2.y = fmaf(hv.y, wj.z, a2.y);
            a2.z = fmaf(hv.z, wj.z, a2.z); a2.w = fmaf(hv.w, wj.z, a2.w);
            a3.x = fmaf(hv.x, wj.w, a3.x); a3.y = fmaf(hv.y, wj.w, a3.y);
            a3.z = fmaf(hv.z, wj.w, a3.z); a3.w = fmaf(hv.w, wj.w, a3.w);
        }
        __syncwarp();
    }
    #pragma unroll
    for (int o = 16; o > 0; o >>= 1) {
        denl.x += __shfl_xor_sync(0xffffffff, denl.x, o);
        denl.y += __shfl_xor_sync(0xffffffff, denl.y, o);
        denl.z += __shfl_xor_sync(0xffffffff, denl.z, o);
        denl.w += __shfl_xor_sync(0xffffffff, denl.w, o);
    }
    float i0 = denl.x > 0.f ? 1.f / denl.x : 0.f;
    float i1 = denl.y > 0.f ? 1.f / denl.y : 0.f;
    float i2 = denl.z > 0.f ? 1.f / denl.z : 0.f;
    float i3 = denl.w > 0.f ? 1.f / denl.w : 0.f;
    a0.x *= i0; a0.y *= i0; a0.z *= i0; a0.w *= i0;
    a1.x *= i1; a1.y *= i1; a1.z *= i1; a1.w *= i1;
    a2.x *= i2; a2.y *= i2; a2.z *= i2; a2.w *= i2;
    a3.x *= i3; a3.y *= i3; a3.z *= i3; a3.w *= i3;
    size_t ob = (size_t)n * 512 + lane * 4;
    store_pair4(g_ghh, g_ghl, ob + 0 * 128, a0);
    store_pair4(g_ghh, g_ghl, ob + 1 * 128, a1);
    store_pair4(g_ghh, g_ghl, ob + 2 * 128, a2);
    store_pair4(g_ghh, g_ghl, ob + 3 * 128, a3);
}

// ---------------- launch ----------------
extern "C" void kernel_launch(void* const* d_in, const int* in_sizes, int n_in,
                              void* d_out, int out_size) {
    const float* x      = (const float*)d_in[0];
    const int*   ei     = (const int*)d_in[1];
    const float* W_l    = (const float*)d_in[2];
    const float* W_r    = (const float*)d_in[3];
    const float* b_sage = (const float*)d_in[4];
    const float* W_src  = (const float*)d_in[5];
    const float* W_dst  = (const float*)d_in[6];
    const float* att_s  = (const float*)d_in[7];
    const float* att_d  = (const float*)d_in[8];
    const float* b_gat  = (const float*)d_in[9];
    const float* W_lin  = (const float*)d_in[10];
    const float* b_lin  = (const float*)d_in[11];
    float* out = (float*)d_out;

    int N = in_sizes[0] / DF;
    int E = in_sizes[1] / 2;

    float* p_h;
    int* p_deg;
    __nv_bfloat16 *p_xh, *p_xl, *p_sxh, *p_sxl, *p_ghh, *p_ghl, *p_goh, *p_gol;
    __nv_bfloat16 *p_wlh, *p_wll, *p_wrh, *p_wrl, *p_bsh, *p_bsl, *p_wlinh, *p_wlinl;
    cudaGetSymbolAddress((void**)&p_h, g_h);
    cudaGetSymbolAddress((void**)&p_deg, g_deg);
    cudaGetSymbolAddress((void**)&p_xh, g_xh);
    cudaGetSymbolAddress((void**)&p_xl, g_xl);
    cudaGetSymbolAddress((void**)&p_sxh, g_sxh);
    cudaGetSymbolAddress((void**)&p_sxl, g_sxl);
    cudaGetSymbolAddress((void**)&p_ghh, g_ghh);
    cudaGetSymbolAddress((void**)&p_ghl, g_ghl);
    cudaGetSymbolAddress((void**)&p_goh, g_goh);
    cudaGetSymbolAddress((void**)&p_gol, g_gol);
    cudaGetSymbolAddress((void**)&p_wlh, g_wlh);
    cudaGetSymbolAddress((void**)&p_wll, g_wll);
    cudaGetSymbolAddress((void**)&p_wrh, g_wrh);
    cudaGetSymbolAddress((void**)&p_wrl, g_wrl);
    cudaGetSymbolAddress((void**)&p_bsh, g_bsh);
    cudaGetSymbolAddress((void**)&p_bsl, g_bsl);
    cudaGetSymbolAddress((void**)&p_wlinh, g_wlinh);
    cudaGetSymbolAddress((void**)&p_wlinl, g_wlinl);

    cudaFuncSetAttribute(k_gemm_tc3, cudaFuncAttributeMaxDynamicSharedMemorySize, SMEM_BYTES3);

    const int T = 256;
    int edgeBlocks = (E + T - 1) / T;
    int nodeWarpBlocks = (N * 32 + T - 1) / T;

    // ---- CSR build ----
    k_zero_int<<<(N + T - 1) / T, T>>>(p_deg, N);
    k_count<<<edgeBlocks, T>>>(ei, E);
    k_scan<<<1, 1024>>>(N);
    k_csr_scatter<<<edgeBlocks, T>>>(ei, E);

    // ---- fused operand prep ----
    int n4x = N * DF / 4;
    int prep_total = n4x + 16384 + 16384 + 65536 + 8192 + 512;
    k_prep_all<<<(prep_total + T - 1) / T, T>>>(x, W_l, W_r, W_src, W_dst,
                                                att_s, att_d, W_lin, n4x);

    int gx = (N + TBM - 1) / TBM;

    // ---- SAGE ----
    k_sage_gather<<<nodeWarpBlocks, T>>>(x, N);
    dim3 g1(gx, DF / TBN);
    k_gemm_tc3<<<g1, 256, SMEM_BYTES3>>>(p_sxh, p_sxl, p_wlh, p_wll,
                                         p_xh, p_xl, p_wrh, p_wrl,
                                         b_sage, p_h, nullptr, nullptr,
                                         N, 128, DF, 1);

    // ---- GAT ----
    k_asd<<<nodeWarpBlocks, T>>>(N);
    k_gat_gather<<<nodeWarpBlocks, T>>>(N);
    k_gemm_tc3<<<g1, 256, SMEM_BYTES3>>>(p_ghh, p_ghl, p_bsh, p_bsl,
                                         nullptr, nullptr, nullptr, nullptr,
                                         b_gat, nullptr, p_goh, p_gol,
                                         N, 512, DF, 1);

    // ---- final linear ----
    dim3 g3(gx, 1);
    k_gemm_tc3<<<g3, 256, SMEM_BYTES3>>>(p_goh, p_gol, p_wlinh, p_wlinl,
                                         nullptr, nullptr, nullptr, nullptr,
                                         b_lin, out, nullptr, nullptr,
                                         N, 128, 64, 0);
}